// round 1
// baseline (speedup 1.0000x reference)
#include <cuda_runtime.h>
#include <cstdint>

// Problem constants
#define BATCH 16384
#define NLOC  12
#define FDIM  512
#define HDIM  256

// ---------------- scratch (device globals; no runtime allocation) ----------------
__device__ float g_gq  [BATCH * HDIM];   // global @ Wq + bq
__device__ float g_gv  [BATCH * HDIM];   // global @ Wv + bv
__device__ float g_t   [BATCH * FDIM];   // gq @ Wk^T
__device__ float g_u   [BATCH * FDIM];   // softmax-weighted local rows
__device__ float g_res [BATCH * FDIM];   // lf_mean + b_dr + global
__device__ float g_comb[BATCH * FDIM];   // [ltg | wg]

// ---------------- small PTX helpers ----------------
__device__ __forceinline__ void cp_async16(void* smem, const void* gmem) {
    unsigned s = (unsigned)__cvta_generic_to_shared(smem);
    asm volatile("cp.async.cg.shared.global [%0], [%1], 16;\n" :: "r"(s), "l"(gmem));
}
__device__ __forceinline__ void cp_commit() { asm volatile("cp.async.commit_group;\n"); }
__device__ __forceinline__ void cp_wait0() { asm volatile("cp.async.wait_group 0;\n"); }
__device__ __forceinline__ void cp_wait1() { asm volatile("cp.async.wait_group 1;\n"); }

__device__ __forceinline__ uint32_t f2tf32(float f) {
    uint32_t r;
    asm("cvt.rna.tf32.f32 %0, %1;" : "=r"(r) : "f"(f));
    return r;
}
__device__ __forceinline__ void mma_tf32(float c[4], const uint32_t a[4], const uint32_t b[2]) {
    asm volatile(
        "mma.sync.aligned.m16n8k8.row.col.f32.tf32.tf32.f32 "
        "{%0,%1,%2,%3}, {%4,%5,%6,%7}, {%8,%9}, {%0,%1,%2,%3};\n"
        : "+f"(c[0]), "+f"(c[1]), "+f"(c[2]), "+f"(c[3])
        : "r"(a[0]), "r"(a[1]), "r"(a[2]), "r"(a[3]), "r"(b[0]), "r"(b[1]));
}

// ---------------- generic tf32 GEMM: C = op(A@B) (+bias) (+relu+res) ----------------
// Block tile 128x64, BK=16, 256 threads = 8 warps (4x2 of 32x32 warp tiles).
// TRANSB: B(k,n) = Bm[n*ldb + k]  (used for t = gq @ Wk^T)
// FINAL : C = relu(acc + bias) + resAdd
template<bool TRANSB, bool FINAL>
__global__ void __launch_bounds__(256, 2) gemm_tf32(
    const float* __restrict__ A, const float* __restrict__ Bm,
    const float* __restrict__ bias, const float* __restrict__ resAdd,
    float* __restrict__ C, int M, int N, int K, int lda, int ldb, int ldc)
{
    __shared__ float As[2][128 * 20];   // row-major, stride 20 (bank-conflict free frags)
    __shared__ float Bs[2][1280];       // non-trans: [16][72]; trans: [64][20]

    const int tid  = threadIdx.x;
    const int bm   = blockIdx.y * 128;
    const int bn   = blockIdx.x * 64;
    const int lane = tid & 31, warp = tid >> 5;
    const int wm   = (warp & 3) * 32;
    const int wn   = (warp >> 2) * 32;
    const int g    = lane >> 2, tq = lane & 3;

    float acc[2][4][4];
    #pragma unroll
    for (int mi = 0; mi < 2; mi++)
        #pragma unroll
        for (int ni = 0; ni < 4; ni++)
            #pragma unroll
            for (int i = 0; i < 4; i++) acc[mi][ni][i] = 0.f;

    const int KT = K >> 4;
    const int ar = tid >> 2, ac = (tid & 3) << 2;  // A tile loads (2x float4/thread)

    auto load_tiles = [&](int kt, int bf) {
        const float* Ab = A + (size_t)bm * lda + (kt << 4);
        cp_async16(&As[bf][ar * 20 + ac],        Ab + (size_t)ar * lda + ac);
        cp_async16(&As[bf][(ar + 64) * 20 + ac], Ab + (size_t)(ar + 64) * lda + ac);
        if (TRANSB) {
            int n = tid >> 2, k4 = (tid & 3) << 2;
            cp_async16(&Bs[bf][n * 20 + k4], Bm + (size_t)(bn + n) * ldb + (kt << 4) + k4);
        } else {
            int r = tid >> 4, c4 = (tid & 15) << 2;
            cp_async16(&Bs[bf][r * 72 + c4], Bm + (size_t)((kt << 4) + r) * ldb + bn + c4);
        }
    };

    load_tiles(0, 0);
    cp_commit();
    int buf = 0;
    for (int kt = 0; kt < KT; ++kt) {
        if (kt + 1 < KT) {
            load_tiles(kt + 1, buf ^ 1);
            cp_commit();
            cp_wait1();
        } else {
            cp_wait0();
        }
        __syncthreads();
        #pragma unroll
        for (int ks = 0; ks < 16; ks += 8) {
            uint32_t aF[2][4], bF[4][2];
            #pragma unroll
            for (int mi = 0; mi < 2; mi++) {
                const float* ap = &As[buf][(wm + mi * 16 + g) * 20 + ks + tq];
                aF[mi][0] = f2tf32(ap[0]);
                aF[mi][1] = f2tf32(ap[160]);      // +8 rows
                aF[mi][2] = f2tf32(ap[4]);        // +4 k
                aF[mi][3] = f2tf32(ap[164]);
            }
            #pragma unroll
            for (int ni = 0; ni < 4; ni++) {
                if (TRANSB) {
                    const float* bp = &Bs[buf][(wn + ni * 8 + g) * 20 + ks + tq];
                    bF[ni][0] = f2tf32(bp[0]);
                    bF[ni][1] = f2tf32(bp[4]);
                } else {
                    const float* bp = &Bs[buf][(ks + tq) * 72 + wn + ni * 8 + g];
                    bF[ni][0] = f2tf32(bp[0]);
                    bF[ni][1] = f2tf32(bp[288]);  // +4 k rows
                }
            }
            #pragma unroll
            for (int mi = 0; mi < 2; mi++)
                #pragma unroll
                for (int ni = 0; ni < 4; ni++)
                    mma_tf32(acc[mi][ni], aF[mi], bF[ni]);
        }
        __syncthreads();
        buf ^= 1;
    }

    // epilogue
    #pragma unroll
    for (int mi = 0; mi < 2; mi++)
        #pragma unroll
        for (int ni = 0; ni < 4; ni++) {
            int row = bm + wm + mi * 16 + g;
            int col = bn + wn + ni * 8 + 2 * tq;
            float b0 = bias ? bias[col] : 0.f;
            float b1 = bias ? bias[col + 1] : 0.f;
            float v0 = acc[mi][ni][0] + b0, v1 = acc[mi][ni][1] + b1;
            float v2 = acc[mi][ni][2] + b0, v3 = acc[mi][ni][3] + b1;
            size_t o0 = (size_t)row * ldc + col;
            size_t o1 = (size_t)(row + 8) * ldc + col;
            if (FINAL) {
                v0 = fmaxf(v0, 0.f) + resAdd[o0];
                v1 = fmaxf(v1, 0.f) + resAdd[o0 + 1];
                v2 = fmaxf(v2, 0.f) + resAdd[o1];
                v3 = fmaxf(v3, 0.f) + resAdd[o1 + 1];
            }
            C[o0] = v0; C[o0 + 1] = v1;
            C[o1] = v2; C[o1 + 1] = v3;
        }
}

// ---------------- fused per-row kernel ----------------
// For each batch row b:
//   s2[k] = (1/16) * <local[b,k,:], t[b,:]>  -> softmax -> a2
//   u[b,:]   = sum_k a2[k]  * local[b,k,:]
//   res[b,:] = sum_k wdr[k] * local[b,k,:] + b_dr + global[b,:]
//   comb[b, 256:512] = gv[b,:] * (sum wdr) + b_dr
__global__ void __launch_bounds__(128) row_fused_kernel(
    const float4* __restrict__ local, const float4* __restrict__ t,
    const float4* __restrict__ gv, const float4* __restrict__ gfeat,
    const float* __restrict__ wdr, const float* __restrict__ bdrp,
    float4* __restrict__ u, float4* __restrict__ res, float4* __restrict__ comb)
{
    const int b = blockIdx.x, j = threadIdx.x;
    __shared__ float s_wdr[12], s_red[4][12], s_a2[12], s_S, s_bdr;
    if (j < 12) s_wdr[j] = wdr[j];
    if (j == 0) s_bdr = bdrp[0];

    const float4 tv = t[b * 128 + j];
    float4 lf[12];
    float p[12];
    #pragma unroll
    for (int k = 0; k < 12; k++) {
        lf[k] = local[(size_t)(b * 12 + k) * 128 + j];
        p[k] = lf[k].x * tv.x + lf[k].y * tv.y + lf[k].z * tv.z + lf[k].w * tv.w;
    }
    #pragma unroll
    for (int off = 16; off > 0; off >>= 1)
        #pragma unroll
        for (int k = 0; k < 12; k++)
            p[k] += __shfl_xor_sync(0xffffffffu, p[k], off);
    if ((j & 31) == 0) {
        #pragma unroll
        for (int k = 0; k < 12; k++) s_red[j >> 5][k] = p[k];
    }
    __syncthreads();
    if (j == 0) {
        float s2[12], mx = -1e30f, S = 0.f;
        #pragma unroll
        for (int k = 0; k < 12; k++) {
            s2[k] = (s_red[0][k] + s_red[1][k] + s_red[2][k] + s_red[3][k]) * 0.0625f;
            mx = fmaxf(mx, s2[k]);
            S += s_wdr[k];
        }
        float sum = 0.f;
        #pragma unroll
        for (int k = 0; k < 12; k++) { s2[k] = __expf(s2[k] - mx); sum += s2[k]; }
        const float inv = 1.f / sum;
        #pragma unroll
        for (int k = 0; k < 12; k++) s_a2[k] = s2[k] * inv;
        s_S = S;
    }
    __syncthreads();

    const float bdr = s_bdr;
    float4 uu = make_float4(0.f, 0.f, 0.f, 0.f);
    float4 rr = make_float4(bdr, bdr, bdr, bdr);
    #pragma unroll
    for (int k = 0; k < 12; k++) {
        const float a = s_a2[k], w = s_wdr[k];
        uu.x = fmaf(a, lf[k].x, uu.x); uu.y = fmaf(a, lf[k].y, uu.y);
        uu.z = fmaf(a, lf[k].z, uu.z); uu.w = fmaf(a, lf[k].w, uu.w);
        rr.x = fmaf(w, lf[k].x, rr.x); rr.y = fmaf(w, lf[k].y, rr.y);
        rr.z = fmaf(w, lf[k].z, rr.z); rr.w = fmaf(w, lf[k].w, rr.w);
    }
    const float4 gg = gfeat[b * 128 + j];
    rr.x += gg.x; rr.y += gg.y; rr.z += gg.z; rr.w += gg.w;
    u[b * 128 + j]   = uu;
    res[b * 128 + j] = rr;

    if (j < 64) {
        const float4 gvv = gv[b * 64 + j];
        const float S = s_S;
        comb[b * 128 + 64 + j] =
            make_float4(fmaf(gvv.x, S, bdr), fmaf(gvv.y, S, bdr),
                        fmaf(gvv.z, S, bdr), fmaf(gvv.w, S, bdr));
    }
}

// ---------------- launch ----------------
extern "C" void kernel_launch(void* const* d_in, const int* in_sizes, int n_in,
                              void* d_out, int out_size) {
    const float* gf  = (const float*)d_in[0];   // [B, F]
    const float* lf  = (const float*)d_in[1];   // [B, 12, F]
    const float* Wq  = (const float*)d_in[2];   // [F, H]
    const float* bq  = (const float*)d_in[3];   // [H]
    // d_in[4] = Wk, d_in[5] = bk (bk is softmax-invariant; dropped exactly)
    const float* Wk  = (const float*)d_in[4];
    const float* Wv  = (const float*)d_in[6];   // [F, H]
    const float* bv  = (const float*)d_in[7];   // [H]
    const float* wdr = (const float*)d_in[8];   // [12]
    const float* bdr = (const float*)d_in[9];   // scalar
    const float* Wf  = (const float*)d_in[10];  // [2H, F]
    const float* bf  = (const float*)d_in[11];  // [F]
    float* out = (float*)d_out;

    float *gq, *gv, *t, *u, *res, *comb;
    cudaGetSymbolAddress((void**)&gq,   g_gq);
    cudaGetSymbolAddress((void**)&gv,   g_gv);
    cudaGetSymbolAddress((void**)&t,    g_t);
    cudaGetSymbolAddress((void**)&u,    g_u);
    cudaGetSymbolAddress((void**)&res,  g_res);
    cudaGetSymbolAddress((void**)&comb, g_comb);

    const dim3 blk(256);

    // 1) gq = global @ Wq + bq     [B,256], K=512
    gemm_tf32<false, false><<<dim3(HDIM / 64, BATCH / 128), blk>>>(
        gf, Wq, bq, nullptr, gq, BATCH, HDIM, FDIM, FDIM, HDIM, HDIM);
    // 2) gv = global @ Wv + bv     [B,256], K=512
    gemm_tf32<false, false><<<dim3(HDIM / 64, BATCH / 128), blk>>>(
        gf, Wv, bv, nullptr, gv, BATCH, HDIM, FDIM, FDIM, HDIM, HDIM);
    // 3) t = gq @ Wk^T             [B,512], K=256  (Wk is [F,H] row-major)
    gemm_tf32<true, false><<<dim3(FDIM / 64, BATCH / 128), blk>>>(
        gq, Wk, nullptr, nullptr, t, BATCH, FDIM, HDIM, HDIM, HDIM, FDIM);
    // 4) fused row kernel: softmax, u, res, wg
    row_fused_kernel<<<BATCH, 128>>>(
        (const float4*)lf, (const float4*)t, (const float4*)gv, (const float4*)gf,
        wdr, bdr, (float4*)u, (float4*)res, (float4*)comb);
    // 5) ltg = u @ Wv + bv  -> comb[:, 0:256]   (ldc = 512)
    gemm_tf32<false, false><<<dim3(HDIM / 64, BATCH / 128), blk>>>(
        u, Wv, bv, nullptr, comb, BATCH, HDIM, FDIM, FDIM, HDIM, FDIM);
    // 6) out = relu(comb @ Wf + bf) + res       [B,512], K=512
    gemm_tf32<false, true><<<dim3(FDIM / 64, BATCH / 128), blk>>>(
        comb, Wf, bf, res, out, BATCH, FDIM, FDIM, FDIM, FDIM, FDIM);
}

// round 4
// speedup vs baseline: 1.0528x; 1.0528x over previous
#include <cuda_runtime.h>
#include <cuda_fp16.h>
#include <cstdint>

// Problem constants
#define BATCH 16384
#define NLOC  12
#define FDIM  512
#define HDIM  256

// ---------------- scratch (device globals; no runtime allocation) ----------------
__device__ float  g_t   [BATCH * FDIM];     // gf @ M0 + c0
__device__ float  g_res [BATCH * FDIM];     // lf_mean + b_dr + gf
__device__ __half g_gfh [BATCH * FDIM];     // gf as fp16
__device__ __half g_uh  [BATCH * FDIM];     // softmax-weighted local rows (fp16)
__device__ __half g_M0h [FDIM * FDIM];      // (Wq@Wk^T)^T  [N=512, K=512] fp16
__device__ __half g_MMh [FDIM * 2 * FDIM];  // [(Wv@WfTop)^T | S*(Wv@WfBot)^T] fp16
__device__ float  g_WfT [FDIM * FDIM];      // Wf^T
__device__ float  g_c0  [FDIM];
__device__ float  g_c   [FDIM];
__device__ float  g_S   [1];

// ---------------- PTX helpers ----------------
__device__ __forceinline__ void cp_async16(void* smem, const void* gmem) {
    unsigned s = (unsigned)__cvta_generic_to_shared(smem);
    asm volatile("cp.async.cg.shared.global [%0], [%1], 16;\n" :: "r"(s), "l"(gmem));
}
__device__ __forceinline__ void cp_commit() { asm volatile("cp.async.commit_group;\n"); }
__device__ __forceinline__ void cp_wait0() { asm volatile("cp.async.wait_group 0;\n"); }
__device__ __forceinline__ void cp_wait1() { asm volatile("cp.async.wait_group 1;\n"); }

__device__ __forceinline__ uint32_t f2tf32(float f) {
    uint32_t r;
    asm("cvt.rna.tf32.f32 %0, %1;" : "=r"(r) : "f"(f));
    return r;
}
__device__ __forceinline__ void mma_tf32(float c[4], const uint32_t a[4], const uint32_t b[2]) {
    asm volatile(
        "mma.sync.aligned.m16n8k8.row.col.f32.tf32.tf32.f32 "
        "{%0,%1,%2,%3}, {%4,%5,%6,%7}, {%8,%9}, {%0,%1,%2,%3};\n"
        : "+f"(c[0]), "+f"(c[1]), "+f"(c[2]), "+f"(c[3])
        : "r"(a[0]), "r"(a[1]), "r"(a[2]), "r"(a[3]), "r"(b[0]), "r"(b[1]));
}
__device__ __forceinline__ void mma_f16(float c[4], const uint32_t a[4], const uint32_t b[2]) {
    asm volatile(
        "mma.sync.aligned.m16n8k16.row.col.f32.f16.f16.f32 "
        "{%0,%1,%2,%3}, {%4,%5,%6,%7}, {%8,%9}, {%0,%1,%2,%3};\n"
        : "+f"(c[0]), "+f"(c[1]), "+f"(c[2]), "+f"(c[3])
        : "r"(a[0]), "r"(a[1]), "r"(a[2]), "r"(a[3]), "r"(b[0]), "r"(b[1]));
}

// ================= fp16 tensor-core GEMM =================
// C[M,512] = A[M,K] @ MMt^T + cvec, block tile 128x128, BK=32, 256 thr = 8 warps (32m x 64n).
// A half [*,512] row-major; SPLIT: kt >= KT/2 reads from A1 (concat along K).
// Bt half [N, K] row-major (K-major).  FINAL: C = relu(D + cvec) + res.
template<int KT, bool SPLIT, bool FINAL>
__global__ void __launch_bounds__(256, 2) hgemm(
    const __half* __restrict__ A0, const __half* __restrict__ A1,
    const __half* __restrict__ Bt, int ldb,
    const float* __restrict__ cvec, const float* __restrict__ res,
    float* __restrict__ C)
{
    __shared__ __half As[2][128 * 40];   // 32 data halves + 8 pad per row
    __shared__ __half Bs[2][128 * 40];

    const int tid = threadIdx.x;
    const int wid = tid >> 5, lane = tid & 31;
    const int bm = blockIdx.y * 128, bn = blockIdx.x * 128;
    const int wm = (wid & 3) * 32, wn = (wid >> 2) * 64;
    const int g = lane >> 2, tq = lane & 3;

    float acc[2][8][4];
    #pragma unroll
    for (int mi = 0; mi < 2; mi++)
        #pragma unroll
        for (int ni = 0; ni < 8; ni++)
            #pragma unroll
            for (int i = 0; i < 4; i++) acc[mi][ni][i] = 0.f;

    // 512 16B-chunks per operand tile; 2 per thread
    const int row0 = tid >> 2, c16 = tid & 3;   // chunk c = i*256 + tid -> row = c>>2

    auto load_tile = [&](int kt, int bf) {
        const __half* Ag = A0;
        int ktA = kt;
        if (SPLIT && kt >= KT / 2) { Ag = A1; ktA = kt - KT / 2; }
        #pragma unroll
        for (int i = 0; i < 2; i++) {
            int row = row0 + i * 64;
            cp_async16(&As[bf][row * 40 + c16 * 8],
                       Ag + (size_t)(bm + row) * 512 + ktA * 32 + c16 * 8);
            cp_async16(&Bs[bf][row * 40 + c16 * 8],
                       Bt + (size_t)(bn + row) * ldb + kt * 32 + c16 * 8);
        }
    };

    load_tile(0, 0);
    cp_commit();
    int buf = 0;
    for (int kt = 0; kt < KT; ++kt) {
        if (kt + 1 < KT) { load_tile(kt + 1, buf ^ 1); cp_commit(); cp_wait1(); }
        else cp_wait0();
        __syncthreads();
        #pragma unroll
        for (int ks = 0; ks < 32; ks += 16) {
            uint32_t aF[2][4], bF[8][2];
            #pragma unroll
            for (int mi = 0; mi < 2; mi++) {
                const __half* ap = &As[buf][(wm + mi * 16 + g) * 40 + ks + 2 * tq];
                aF[mi][0] = *(const uint32_t*)(ap);
                aF[mi][1] = *(const uint32_t*)(ap + 8 * 40);   // +8 rows
                aF[mi][2] = *(const uint32_t*)(ap + 8);        // +8 k
                aF[mi][3] = *(const uint32_t*)(ap + 8 * 40 + 8);
            }
            #pragma unroll
            for (int ni = 0; ni < 8; ni++) {
                const __half* bp = &Bs[buf][(wn + ni * 8 + g) * 40 + ks + 2 * tq];
                bF[ni][0] = *(const uint32_t*)(bp);
                bF[ni][1] = *(const uint32_t*)(bp + 8);
            }
            #pragma unroll
            for (int mi = 0; mi < 2; mi++)
                #pragma unroll
                for (int ni = 0; ni < 8; ni++)
                    mma_f16(acc[mi][ni], aF[mi], bF[ni]);
        }
        __syncthreads();
        buf ^= 1;
    }

    // epilogue
    #pragma unroll
    for (int mi = 0; mi < 2; mi++)
        #pragma unroll
        for (int ni = 0; ni < 8; ni++) {
            int row = bm + wm + mi * 16 + g;
            int col = bn + wn + ni * 8 + 2 * tq;
            float b0 = cvec[col], b1 = cvec[col + 1];
            float v0 = acc[mi][ni][0] + b0, v1 = acc[mi][ni][1] + b1;
            float v2 = acc[mi][ni][2] + b0, v3 = acc[mi][ni][3] + b1;
            size_t o0 = (size_t)row * 512 + col;
            size_t o1 = (size_t)(row + 8) * 512 + col;
            if (FINAL) {
                const float2 r0 = *(const float2*)(res + o0);
                const float2 r1 = *(const float2*)(res + o1);
                v0 = fmaxf(v0, 0.f) + r0.x;
                v1 = fmaxf(v1, 0.f) + r0.y;
                v2 = fmaxf(v2, 0.f) + r1.x;
                v3 = fmaxf(v3, 0.f) + r1.y;
            }
            *(float2*)(C + o0) = make_float2(v0, v1);
            *(float2*)(C + o1) = make_float2(v2, v3);
        }
}

// ================= legacy tf32 GEMM for small prep matrices (fp16 output) ======
// C[m][n] (half) = alpha * sum_h A[m][h] * Bm[n][h]   (TRANSB semantics)
template<bool TRANSB>
__global__ void __launch_bounds__(256, 2) gemm_prep(
    const float* __restrict__ A, const float* __restrict__ Bm,
    const float* __restrict__ alphaPtr,
    __half* __restrict__ C, int K, int lda, int ldb, int ldc)
{
    __shared__ float As[2][128 * 20];
    __shared__ float Bs[2][1280];

    const int tid = threadIdx.x;
    const int bm = blockIdx.y * 128, bn = blockIdx.x * 64;
    const int lane = tid & 31, warp = tid >> 5;
    const int wm = (warp & 3) * 32, wn = (warp >> 2) * 32;
    const int g = lane >> 2, tq = lane & 3;

    float acc[2][4][4];
    #pragma unroll
    for (int mi = 0; mi < 2; mi++)
        #pragma unroll
        for (int ni = 0; ni < 4; ni++)
            #pragma unroll
            for (int i = 0; i < 4; i++) acc[mi][ni][i] = 0.f;

    const int KT = K >> 4;
    const int ar = tid >> 2, ac = (tid & 3) << 2;

    auto load_tiles = [&](int kt, int bf) {
        const float* Ab = A + (size_t)bm * lda + (kt << 4);
        cp_async16(&As[bf][ar * 20 + ac],        Ab + (size_t)ar * lda + ac);
        cp_async16(&As[bf][(ar + 64) * 20 + ac], Ab + (size_t)(ar + 64) * lda + ac);
        if (TRANSB) {
            int n = tid >> 2, k4 = (tid & 3) << 2;
            cp_async16(&Bs[bf][n * 20 + k4], Bm + (size_t)(bn + n) * ldb + (kt << 4) + k4);
        } else {
            int r = tid >> 4, c4 = (tid & 15) << 2;
            cp_async16(&Bs[bf][r * 72 + c4], Bm + (size_t)((kt << 4) + r) * ldb + bn + c4);
        }
    };

    load_tiles(0, 0);
    cp_commit();
    int buf = 0;
    for (int kt = 0; kt < KT; ++kt) {
        if (kt + 1 < KT) { load_tiles(kt + 1, buf ^ 1); cp_commit(); cp_wait1(); }
        else cp_wait0();
        __syncthreads();
        #pragma unroll
        for (int ks = 0; ks < 16; ks += 8) {
            uint32_t aF[2][4], bF[4][2];
            #pragma unroll
            for (int mi = 0; mi < 2; mi++) {
                const float* ap = &As[buf][(wm + mi * 16 + g) * 20 + ks + tq];
                aF[mi][0] = f2tf32(ap[0]);
                aF[mi][1] = f2tf32(ap[160]);
                aF[mi][2] = f2tf32(ap[4]);
                aF[mi][3] = f2tf32(ap[164]);
            }
            #pragma unroll
            for (int ni = 0; ni < 4; ni++) {
                if (TRANSB) {
                    const float* bp = &Bs[buf][(wn + ni * 8 + g) * 20 + ks + tq];
                    bF[ni][0] = f2tf32(bp[0]);
                    bF[ni][1] = f2tf32(bp[4]);
                } else {
                    const float* bp = &Bs[buf][(ks + tq) * 72 + wn + ni * 8 + g];
                    bF[ni][0] = f2tf32(bp[0]);
                    bF[ni][1] = f2tf32(bp[288]);
                }
            }
            #pragma unroll
            for (int mi = 0; mi < 2; mi++)
                #pragma unroll
                for (int ni = 0; ni < 4; ni++)
                    mma_tf32(acc[mi][ni], aF[mi], bF[ni]);
        }
        __syncthreads();
        buf ^= 1;
    }

    const float alpha = alphaPtr ? *alphaPtr : 1.f;
    #pragma unroll
    for (int mi = 0; mi < 2; mi++)
        #pragma unroll
        for (int ni = 0; ni < 4; ni++) {
            int r0 = bm + wm + mi * 16 + g;
            int cc = bn + wn + ni * 8 + 2 * tq;
            size_t o0 = (size_t)r0 * ldc + cc;
            size_t o1 = (size_t)(r0 + 8) * ldc + cc;
            C[o0]     = __float2half(acc[mi][ni][0] * alpha);
            C[o0 + 1] = __float2half(acc[mi][ni][1] * alpha);
            C[o1]     = __float2half(acc[mi][ni][2] * alpha);
            C[o1 + 1] = __float2half(acc[mi][ni][3] * alpha);
        }
}

// ================= prep: S, c0, c =================
__global__ void __launch_bounds__(512) prep_vec(
    const float* __restrict__ wdr, const float* __restrict__ bdrp,
    const float* __restrict__ bq, const float* __restrict__ Wk,
    const float* __restrict__ bv, const float* __restrict__ Wf,
    const float* __restrict__ bfv,
    float* __restrict__ c0, float* __restrict__ c, float* __restrict__ Sout)
{
    __shared__ float sS;
    const int f = threadIdx.x;
    if (f == 0) {
        float S = 0.f;
        #pragma unroll
        for (int k = 0; k < NLOC; k++) S += wdr[k];
        sS = S;
        Sout[0] = S;
    }
    __syncthreads();
    const float S = sS, bd = bdrp[0];
    float a0 = 0.f;
    for (int h = 0; h < HDIM; h++) a0 += bq[h] * Wk[f * HDIM + h];
    c0[f] = a0;
    float a1 = bfv[f];
    for (int h = 0; h < HDIM; h++) {
        a1 += bv[h] * Wf[h * FDIM + f];
        a1 += (S * bv[h] + bd) * Wf[(HDIM + h) * FDIM + f];
    }
    c[f] = a1;
}

// ================= transpose Wf -> WfT =================
__global__ void __launch_bounds__(256) transpose512(const float* __restrict__ in,
                                                    float* __restrict__ out)
{
    __shared__ float tileS[32][33];
    const int bx = blockIdx.x * 32, by = blockIdx.y * 32;
    const int tx = threadIdx.x & 31, ty = threadIdx.x >> 5;  // 32x8
    #pragma unroll
    for (int i = 0; i < 32; i += 8)
        tileS[ty + i][tx] = in[(size_t)(by + ty + i) * FDIM + bx + tx];
    __syncthreads();
    #pragma unroll
    for (int i = 0; i < 32; i += 8)
        out[(size_t)(bx + ty + i) * FDIM + by + tx] = tileS[tx][ty + i];
}

// ================= fp32 -> fp16 bulk convert =================
__global__ void __launch_bounds__(256) cvt_f2h(const float4* __restrict__ in,
                                               uint2* __restrict__ out, int n4)
{
    int i = blockIdx.x * blockDim.x + threadIdx.x;
    if (i < n4) {
        float4 v = in[i];
        __half2 h0 = __floats2half2_rn(v.x, v.y);
        __half2 h1 = __floats2half2_rn(v.z, v.w);
        uint2 pk;
        pk.x = *(uint32_t*)&h0;
        pk.y = *(uint32_t*)&h1;
        out[i] = pk;
    }
}

// ================= fused per-row kernel =================
// s2[k] = <local[b,k,:], t[b,:]>/16 -> softmax -> a2
// u_h[b,:] (half) = sum_k a2[k] * local[b,k,:]
// res[b,:] = sum_k wdr[k] * local[b,k,:] + b_dr + gf[b,:]
__global__ void __launch_bounds__(128) row_fused_kernel(
    const float4* __restrict__ local, const float4* __restrict__ t,
    const float4* __restrict__ gfeat,
    const float* __restrict__ wdr, const float* __restrict__ bdrp,
    uint2* __restrict__ u_h, float4* __restrict__ res)
{
    const int b = blockIdx.x, j = threadIdx.x;
    __shared__ float s_wdr[12], s_red[4][12], s_a2[12], s_bdr;
    if (j < 12) s_wdr[j] = wdr[j];
    if (j == 0) s_bdr = bdrp[0];

    const float4 tv = t[b * 128 + j];
    float4 lf[12];
    float p[12];
    #pragma unroll
    for (int k = 0; k < 12; k++) {
        lf[k] = local[(size_t)(b * 12 + k) * 128 + j];
        p[k] = lf[k].x * tv.x + lf[k].y * tv.y + lf[k].z * tv.z + lf[k].w * tv.w;
    }
    #pragma unroll
    for (int off = 16; off > 0; off >>= 1)
        #pragma unroll
        for (int k = 0; k < 12; k++)
            p[k] += __shfl_xor_sync(0xffffffffu, p[k], off);
    if ((j & 31) == 0) {
        #pragma unroll
        for (int k = 0; k < 12; k++) s_red[j >> 5][k] = p[k];
    }
    __syncthreads();
    if (j == 0) {
        float s2[12], mx = -1e30f;
        #pragma unroll
        for (int k = 0; k < 12; k++) {
            s2[k] = (s_red[0][k] + s_red[1][k] + s_red[2][k] + s_red[3][k]) * 0.0625f;
            mx = fmaxf(mx, s2[k]);
        }
        float sum = 0.f;
        #pragma unroll
        for (int k = 0; k < 12; k++) { s2[k] = __expf(s2[k] - mx); sum += s2[k]; }
        const float inv = 1.f / sum;
        #pragma unroll
        for (int k = 0; k < 12; k++) s_a2[k] = s2[k] * inv;
    }
    __syncthreads();

    const float bdr = s_bdr;
    float4 uu = make_float4(0.f, 0.f, 0.f, 0.f);
    float4 rr = make_float4(bdr, bdr, bdr, bdr);
    #pragma unroll
    for (int k = 0; k < 12; k++) {
        const float a = s_a2[k], w = s_wdr[k];
        uu.x = fmaf(a, lf[k].x, uu.x); uu.y = fmaf(a, lf[k].y, uu.y);
        uu.z = fmaf(a, lf[k].z, uu.z); uu.w = fmaf(a, lf[k].w, uu.w);
        rr.x = fmaf(w, lf[k].x, rr.x); rr.y = fmaf(w, lf[k].y, rr.y);
        rr.z = fmaf(w, lf[k].z, rr.z); rr.w = fmaf(w, lf[k].w, rr.w);
    }
    const float4 gg = gfeat[b * 128 + j];
    rr.x += gg.x; rr.y += gg.y; rr.z += gg.z; rr.w += gg.w;

    __half2 ha = __floats2half2_rn(uu.x, uu.y);
    __half2 hb = __floats2half2_rn(uu.z, uu.w);
    uint2 pk;
    pk.x = *(uint32_t*)&ha;
    pk.y = *(uint32_t*)&hb;
    u_h[b * 128 + j] = pk;
    res[b * 128 + j] = rr;
}

// ================= launch =================
extern "C" void kernel_launch(void* const* d_in, const int* in_sizes, int n_in,
                              void* d_out, int out_size) {
    const float* gf  = (const float*)d_in[0];   // [B, F]
    const float* lf  = (const float*)d_in[1];   // [B, 12, F]
    const float* Wq  = (const float*)d_in[2];   // [F, H]
    const float* bq  = (const float*)d_in[3];   // [H]
    const float* Wk  = (const float*)d_in[4];   // [F, H]  (bk softmax-invariant: dropped)
    const float* Wv  = (const float*)d_in[6];   // [F, H]
    const float* bv  = (const float*)d_in[7];   // [H]
    const float* wdr = (const float*)d_in[8];   // [12]
    const float* bdr = (const float*)d_in[9];   // scalar
    const float* Wf  = (const float*)d_in[10];  // [2H, F]
    const float* bfv = (const float*)d_in[11];  // [F]
    float* out = (float*)d_out;

    float *t, *res, *WfT, *c0, *c, *S;
    __half *gfh, *uh, *M0h, *MMh;
    cudaGetSymbolAddress((void**)&t,   g_t);
    cudaGetSymbolAddress((void**)&res, g_res);
    cudaGetSymbolAddress((void**)&gfh, g_gfh);
    cudaGetSymbolAddress((void**)&uh,  g_uh);
    cudaGetSymbolAddress((void**)&M0h, g_M0h);
    cudaGetSymbolAddress((void**)&MMh, g_MMh);
    cudaGetSymbolAddress((void**)&WfT, g_WfT);
    cudaGetSymbolAddress((void**)&c0,  g_c0);
    cudaGetSymbolAddress((void**)&c,   g_c);
    cudaGetSymbolAddress((void**)&S,   g_S);

    // 1) scalars + folded bias vectors
    prep_vec<<<1, 512>>>(wdr, bdr, bq, Wk, bv, Wf, bfv, c0, c, S);
    // 2) WfT = Wf^T
    transpose512<<<dim3(16, 16), 256>>>(Wf, WfT);
    // 3) M0h[m][n] = Wk[m]·Wq[n]   (K-major weight for GEMM1), fp16
    gemm_prep<true><<<dim3(8, 4), 256>>>(Wk, Wq, nullptr, M0h, HDIM, HDIM, HDIM, FDIM);
    // 4) MMh[m][0:512]  = sum_{h<256} WfT[m,h] * Wv[n,h]
    gemm_prep<true><<<dim3(8, 4), 256>>>(WfT, Wv, nullptr, MMh, HDIM, FDIM, HDIM, 2 * FDIM);
    // 5) MMh[m][512:1024] = S * sum_{h<256} WfT[m,256+h] * Wv[n,h]
    gemm_prep<true><<<dim3(8, 4), 256>>>(WfT + HDIM, Wv, S, MMh + FDIM, HDIM, FDIM, HDIM, 2 * FDIM);
    // 6) gf -> fp16
    cvt_f2h<<<(BATCH * FDIM / 4 + 255) / 256, 256>>>(
        (const float4*)gf, (uint2*)gfh, BATCH * FDIM / 4);
    // 7) t = gf_h @ M0 + c0   [B,512], K=512  (fp16 tensor cores)
    hgemm<16, false, false><<<dim3(FDIM / 128, BATCH / 128), 256>>>(
        gfh, nullptr, M0h, FDIM, c0, nullptr, t);
    // 8) row kernel: softmax weights, u (fp16), res
    row_fused_kernel<<<BATCH, 128>>>(
        (const float4*)lf, (const float4*)t, (const float4*)gf,
        wdr, bdr, (uint2*)uh, (float4*)res);
    // 9) out = relu([u|gf] @ MM + c) + res   [B,512], K=1024  (fp16 tensor cores)
    hgemm<32, true, true><<<dim3(FDIM / 128, BATCH / 128), 256>>>(
        uh, gfh, MMh, 2 * FDIM, c, res, out);
}

// round 5
// speedup vs baseline: 1.5484x; 1.4707x over previous
#include <cuda_runtime.h>
#include <cuda_fp16.h>
#include <cstdint>

// Problem constants
#define BATCH 16384
#define NLOC  12
#define FDIM  512
#define HDIM  256

// ---------------- scratch (device globals; no runtime allocation) ----------------
__device__ float  g_t   [BATCH * FDIM];     // gf @ M0 + c0
__device__ float  g_res [BATCH * FDIM];     // lf_mean + b_dr + gf
__device__ __half g_gfh [BATCH * FDIM];     // gf as fp16
__device__ __half g_uh  [BATCH * FDIM];     // softmax-weighted local rows (fp16)
__device__ __half g_M0h [FDIM * FDIM];      // (Wq@Wk^T)^T  [N=512, K=512] fp16
__device__ __half g_MMh [FDIM * 2 * FDIM];  // [(Wv@WfTop)^T | S*(Wv@WfBot)^T] fp16
__device__ float  g_WfT [FDIM * FDIM];      // Wf^T
__device__ float  g_c0  [FDIM];
__device__ float  g_c   [FDIM];
__device__ float  g_S   [1];

// ---------------- PTX helpers ----------------
__device__ __forceinline__ void cp_async16(void* smem, const void* gmem) {
    unsigned s = (unsigned)__cvta_generic_to_shared(smem);
    asm volatile("cp.async.cg.shared.global [%0], [%1], 16;\n" :: "r"(s), "l"(gmem));
}
__device__ __forceinline__ void cp_commit() { asm volatile("cp.async.commit_group;\n"); }
__device__ __forceinline__ void cp_wait0() { asm volatile("cp.async.wait_group 0;\n"); }
__device__ __forceinline__ void cp_wait1() { asm volatile("cp.async.wait_group 1;\n"); }

__device__ __forceinline__ uint32_t f2tf32(float f) {
    uint32_t r;
    asm("cvt.rna.tf32.f32 %0, %1;" : "=r"(r) : "f"(f));
    return r;
}
__device__ __forceinline__ void mma_tf32(float c[4], const uint32_t a[4], const uint32_t b[2]) {
    asm volatile(
        "mma.sync.aligned.m16n8k8.row.col.f32.tf32.tf32.f32 "
        "{%0,%1,%2,%3}, {%4,%5,%6,%7}, {%8,%9}, {%0,%1,%2,%3};\n"
        : "+f"(c[0]), "+f"(c[1]), "+f"(c[2]), "+f"(c[3])
        : "r"(a[0]), "r"(a[1]), "r"(a[2]), "r"(a[3]), "r"(b[0]), "r"(b[1]));
}
__device__ __forceinline__ void mma_f16(float c[4], const uint32_t a[4], const uint32_t b[2]) {
    asm volatile(
        "mma.sync.aligned.m16n8k16.row.col.f32.f16.f16.f32 "
        "{%0,%1,%2,%3}, {%4,%5,%6,%7}, {%8,%9}, {%0,%1,%2,%3};\n"
        : "+f"(c[0]), "+f"(c[1]), "+f"(c[2]), "+f"(c[3])
        : "r"(a[0]), "r"(a[1]), "r"(a[2]), "r"(a[3]), "r"(b[0]), "r"(b[1]));
}
__device__ __forceinline__ void ldsm4(uint32_t& r0, uint32_t& r1, uint32_t& r2, uint32_t& r3,
                                      uint32_t addr) {
    asm volatile("ldmatrix.sync.aligned.m8n8.x4.shared.b16 {%0,%1,%2,%3}, [%4];"
                 : "=r"(r0), "=r"(r1), "=r"(r2), "=r"(r3) : "r"(addr));
}

// ================= fp16 tensor-core GEMM (ldmatrix fragment loads) =============
// C[M,512] = A[M,K] @ Bt^T + cvec, block tile 128x128, BK=32, 256 thr = 8 warps (32m x 64n).
// A half [*,512] row-major; SPLIT: kt >= KT/2 reads from A1 (concat along K).
// Bt half [N, K] row-major (K-major).  FINAL: C = relu(D + cvec) + res.
template<int KT, bool SPLIT, bool FINAL>
__global__ void __launch_bounds__(256, 2) hgemm(
    const __half* __restrict__ A0, const __half* __restrict__ A1,
    const __half* __restrict__ Bt, int ldb,
    const float* __restrict__ cvec, const float* __restrict__ res,
    float* __restrict__ C)
{
    __shared__ __half As[2][128 * 40];   // 32 data halves + 8 pad per row (80B stride)
    __shared__ __half Bs[2][128 * 40];

    const int tid = threadIdx.x;
    const int wid = tid >> 5, lane = tid & 31;
    const int bm = blockIdx.y * 128, bn = blockIdx.x * 128;
    const int wm = (wid & 3) * 32, wn = (wid >> 2) * 64;
    const int g = lane >> 2, tq = lane & 3;

    float acc[2][8][4];
    #pragma unroll
    for (int mi = 0; mi < 2; mi++)
        #pragma unroll
        for (int ni = 0; ni < 8; ni++)
            #pragma unroll
            for (int i = 0; i < 4; i++) acc[mi][ni][i] = 0.f;

    // ldmatrix per-lane address components
    const int q = lane >> 3, r8 = lane & 7;
    const int qRow = (q & 1) * 8 + r8;       // row-within-16 for this lane's matrix
    const int qCol = (q >> 1) * 8;           // k offset (0 or 8)
    const uint32_t aBase = (uint32_t)__cvta_generic_to_shared(&As[0][0]);
    const uint32_t bBase = (uint32_t)__cvta_generic_to_shared(&Bs[0][0]);
    const uint32_t aLane = ((wm + qRow) * 40 + qCol) * 2;   // byte offsets
    const uint32_t bLane = ((wn + qRow) * 40 + qCol) * 2;

    const int row0 = tid >> 2, c16 = tid & 3;

    auto load_tile = [&](int kt, int bf) {
        const __half* Ag = A0;
        int ktA = kt;
        if (SPLIT && kt >= KT / 2) { Ag = A1; ktA = kt - KT / 2; }
        #pragma unroll
        for (int i = 0; i < 2; i++) {
            int row = row0 + i * 64;
            cp_async16(&As[bf][row * 40 + c16 * 8],
                       Ag + (size_t)(bm + row) * 512 + ktA * 32 + c16 * 8);
            cp_async16(&Bs[bf][row * 40 + c16 * 8],
                       Bt + (size_t)(bn + row) * ldb + kt * 32 + c16 * 8);
        }
    };

    load_tile(0, 0);
    cp_commit();
    int buf = 0;
    for (int kt = 0; kt < KT; ++kt) {
        if (kt + 1 < KT) { load_tile(kt + 1, buf ^ 1); cp_commit(); cp_wait1(); }
        else cp_wait0();
        __syncthreads();
        const uint32_t aB = aBase + buf * (128 * 40 * 2) + aLane;
        const uint32_t bB = bBase + buf * (128 * 40 * 2) + bLane;
        #pragma unroll
        for (int ks = 0; ks < 32; ks += 16) {
            uint32_t aF[2][4], bF[8][2];
            #pragma unroll
            for (int mi = 0; mi < 2; mi++)
                ldsm4(aF[mi][0], aF[mi][1], aF[mi][2], aF[mi][3],
                      aB + (mi * 16 * 40 + ks) * 2);
            #pragma unroll
            for (int nb = 0; nb < 4; nb++) {
                uint32_t t0, t1, t2, t3;
                ldsm4(t0, t1, t2, t3, bB + (nb * 16 * 40 + ks) * 2);
                bF[2 * nb][0] = t0; bF[2 * nb + 1][0] = t1;
                bF[2 * nb][1] = t2; bF[2 * nb + 1][1] = t3;
            }
            #pragma unroll
            for (int mi = 0; mi < 2; mi++)
                #pragma unroll
                for (int ni = 0; ni < 8; ni++)
                    mma_f16(acc[mi][ni], aF[mi], bF[ni]);
        }
        __syncthreads();
        buf ^= 1;
    }

    // epilogue
    #pragma unroll
    for (int mi = 0; mi < 2; mi++)
        #pragma unroll
        for (int ni = 0; ni < 8; ni++) {
            int row = bm + wm + mi * 16 + g;
            int col = bn + wn + ni * 8 + 2 * tq;
            float b0 = cvec[col], b1 = cvec[col + 1];
            float v0 = acc[mi][ni][0] + b0, v1 = acc[mi][ni][1] + b1;
            float v2 = acc[mi][ni][2] + b0, v3 = acc[mi][ni][3] + b1;
            size_t o0 = (size_t)row * 512 + col;
            size_t o1 = (size_t)(row + 8) * 512 + col;
            if (FINAL) {
                const float2 r0 = *(const float2*)(res + o0);
                const float2 r1 = *(const float2*)(res + o1);
                v0 = fmaxf(v0, 0.f) + r0.x;
                v1 = fmaxf(v1, 0.f) + r0.y;
                v2 = fmaxf(v2, 0.f) + r1.x;
                v3 = fmaxf(v3, 0.f) + r1.y;
            }
            *(float2*)(C + o0) = make_float2(v0, v1);
            *(float2*)(C + o1) = make_float2(v2, v3);
        }
}

// ================= combined prep GEMMs (all three weight products) =============
// 64x64 tiles, 128 threads, K=256, tf32 mma, C output fp16.
// z=0: M0h[m][n] = Wk[m]·Wq[n]            (ldc=512)
// z=1: MMh[m][n]       = WfT[m, 0:256]·Wv[n]   (ldc=1024)
// z=2: MMh[m][512 + n] = S * WfT[m,256:512]·Wv[n]
__global__ void __launch_bounds__(128, 4) prep_all(
    const float* __restrict__ Wk, const float* __restrict__ Wq,
    const float* __restrict__ WfT, const float* __restrict__ Wv,
    const float* __restrict__ Sptr,
    __half* __restrict__ M0h, __half* __restrict__ MMh)
{
    __shared__ float As[2][64 * 20];
    __shared__ float Bs[2][64 * 20];

    const int z = blockIdx.z;
    const float *A, *Bm;
    __half* C;
    int lda, ldc;
    float alpha = 1.f;
    if (z == 0)      { A = Wk;        lda = 256; Bm = Wq; C = M0h;       ldc = 512;  }
    else if (z == 1) { A = WfT;       lda = 512; Bm = Wv; C = MMh;       ldc = 1024; }
    else             { A = WfT + 256; lda = 512; Bm = Wv; C = MMh + 512; ldc = 1024;
                       alpha = Sptr[0]; }

    const int tid = threadIdx.x;
    const int bm = blockIdx.y * 64, bn = blockIdx.x * 64;
    const int lane = tid & 31, wid = tid >> 5;
    const int wm = (wid & 1) * 32, wn = (wid >> 1) * 32;
    const int g = lane >> 2, tq = lane & 3;

    float acc[2][4][4];
    #pragma unroll
    for (int mi = 0; mi < 2; mi++)
        #pragma unroll
        for (int ni = 0; ni < 4; ni++)
            #pragma unroll
            for (int i = 0; i < 4; i++) acc[mi][ni][i] = 0.f;

    auto load_tiles = [&](int kt, int bf) {
        #pragma unroll
        for (int i = 0; i < 2; i++) {
            int cchunk = i * 128 + tid;
            int row = cchunk >> 2, c4 = (cchunk & 3) << 2;
            cp_async16(&As[bf][row * 20 + c4], A  + (size_t)(bm + row) * lda + kt * 16 + c4);
            cp_async16(&Bs[bf][row * 20 + c4], Bm + (size_t)(bn + row) * 256 + kt * 16 + c4);
        }
    };

    load_tiles(0, 0);
    cp_commit();
    int buf = 0;
    for (int kt = 0; kt < 16; ++kt) {
        if (kt + 1 < 16) { load_tiles(kt + 1, buf ^ 1); cp_commit(); cp_wait1(); }
        else cp_wait0();
        __syncthreads();
        #pragma unroll
        for (int ks = 0; ks < 16; ks += 8) {
            uint32_t aF[2][4], bF[4][2];
            #pragma unroll
            for (int mi = 0; mi < 2; mi++) {
                const float* ap = &As[buf][(wm + mi * 16 + g) * 20 + ks + tq];
                aF[mi][0] = f2tf32(ap[0]);
                aF[mi][1] = f2tf32(ap[160]);
                aF[mi][2] = f2tf32(ap[4]);
                aF[mi][3] = f2tf32(ap[164]);
            }
            #pragma unroll
            for (int ni = 0; ni < 4; ni++) {
                const float* bp = &Bs[buf][(wn + ni * 8 + g) * 20 + ks + tq];
                bF[ni][0] = f2tf32(bp[0]);
                bF[ni][1] = f2tf32(bp[4]);
            }
            #pragma unroll
            for (int mi = 0; mi < 2; mi++)
                #pragma unroll
                for (int ni = 0; ni < 4; ni++)
                    mma_tf32(acc[mi][ni], aF[mi], bF[ni]);
        }
        __syncthreads();
        buf ^= 1;
    }

    #pragma unroll
    for (int mi = 0; mi < 2; mi++)
        #pragma unroll
        for (int ni = 0; ni < 4; ni++) {
            int r0 = bm + wm + mi * 16 + g;
            int cc = bn + wn + ni * 8 + 2 * tq;
            size_t o0 = (size_t)r0 * ldc + cc;
            size_t o1 = (size_t)(r0 + 8) * ldc + cc;
            C[o0]     = __float2half(acc[mi][ni][0] * alpha);
            C[o0 + 1] = __float2half(acc[mi][ni][1] * alpha);
            C[o1]     = __float2half(acc[mi][ni][2] * alpha);
            C[o1 + 1] = __float2half(acc[mi][ni][3] * alpha);
        }
}

// ================= prep: S, c0, c  (warp-per-f, coalesced via WfT) =============
__global__ void __launch_bounds__(128) prep_vec(
    const float* __restrict__ wdr, const float* __restrict__ bdrp,
    const float* __restrict__ bq, const float* __restrict__ Wk,
    const float* __restrict__ bv, const float* __restrict__ WfT,
    const float* __restrict__ bfv,
    float* __restrict__ c0, float* __restrict__ c, float* __restrict__ Sout)
{
    const int wid = threadIdx.x >> 5, lane = threadIdx.x & 31;
    const int f = blockIdx.x * 4 + wid;   // 128 blocks x 4 warps = 512
    float S = (lane < NLOC) ? wdr[lane] : 0.f;
    #pragma unroll
    for (int off = 16; off > 0; off >>= 1) S += __shfl_xor_sync(0xffffffffu, S, off);
    const float bd = bdrp[0];
    if (blockIdx.x == 0 && threadIdx.x == 0) Sout[0] = S;

    float a0 = 0.f, a1 = 0.f;
    for (int h = lane; h < HDIM; h += 32) {
        a0 = fmaf(bq[h], Wk[f * HDIM + h], a0);
        const float bvh = bv[h];
        a1 = fmaf(bvh, WfT[f * FDIM + h], a1);
        a1 = fmaf(fmaf(S, bvh, bd), WfT[f * FDIM + HDIM + h], a1);
    }
    #pragma unroll
    for (int off = 16; off > 0; off >>= 1) {
        a0 += __shfl_xor_sync(0xffffffffu, a0, off);
        a1 += __shfl_xor_sync(0xffffffffu, a1, off);
    }
    if (lane == 0) {
        c0[f] = a0;
        c[f]  = a1 + bfv[f];
    }
}

// ================= transpose Wf -> WfT =================
__global__ void __launch_bounds__(256) transpose512(const float* __restrict__ in,
                                                    float* __restrict__ out)
{
    __shared__ float tileS[32][33];
    const int bx = blockIdx.x * 32, by = blockIdx.y * 32;
    const int tx = threadIdx.x & 31, ty = threadIdx.x >> 5;  // 32x8
    #pragma unroll
    for (int i = 0; i < 32; i += 8)
        tileS[ty + i][tx] = in[(size_t)(by + ty + i) * FDIM + bx + tx];
    __syncthreads();
    #pragma unroll
    for (int i = 0; i < 32; i += 8)
        out[(size_t)(bx + ty + i) * FDIM + by + tx] = tileS[tx][ty + i];
}

// ================= fp32 -> fp16 bulk convert =================
__global__ void __launch_bounds__(256) cvt_f2h(const float4* __restrict__ in,
                                               uint2* __restrict__ out, int n4)
{
    int i = blockIdx.x * blockDim.x + threadIdx.x;
    if (i < n4) {
        float4 v = in[i];
        __half2 h0 = __floats2half2_rn(v.x, v.y);
        __half2 h1 = __floats2half2_rn(v.z, v.w);
        uint2 pk;
        pk.x = *(uint32_t*)&h0;
        pk.y = *(uint32_t*)&h1;
        out[i] = pk;
    }
}

// ================= fused per-row kernel =================
__global__ void __launch_bounds__(128) row_fused_kernel(
    const float4* __restrict__ local, const float4* __restrict__ t,
    const float4* __restrict__ gfeat,
    const float* __restrict__ wdr, const float* __restrict__ bdrp,
    uint2* __restrict__ u_h, float4* __restrict__ res)
{
    const int b = blockIdx.x, j = threadIdx.x;
    __shared__ float s_wdr[12], s_red[4][12], s_a2[12], s_bdr;
    if (j < 12) s_wdr[j] = wdr[j];
    if (j == 0) s_bdr = bdrp[0];

    const float4 tv = t[b * 128 + j];
    float4 lf[12];
    float p[12];
    #pragma unroll
    for (int k = 0; k < 12; k++) {
        lf[k] = local[(size_t)(b * 12 + k) * 128 + j];
        p[k] = lf[k].x * tv.x + lf[k].y * tv.y + lf[k].z * tv.z + lf[k].w * tv.w;
    }
    #pragma unroll
    for (int off = 16; off > 0; off >>= 1)
        #pragma unroll
        for (int k = 0; k < 12; k++)
            p[k] += __shfl_xor_sync(0xffffffffu, p[k], off);
    if ((j & 31) == 0) {
        #pragma unroll
        for (int k = 0; k < 12; k++) s_red[j >> 5][k] = p[k];
    }
    __syncthreads();
    if (j == 0) {
        float s2[12], mx = -1e30f;
        #pragma unroll
        for (int k = 0; k < 12; k++) {
            s2[k] = (s_red[0][k] + s_red[1][k] + s_red[2][k] + s_red[3][k]) * 0.0625f;
            mx = fmaxf(mx, s2[k]);
        }
        float sum = 0.f;
        #pragma unroll
        for (int k = 0; k < 12; k++) { s2[k] = __expf(s2[k] - mx); sum += s2[k]; }
        const float inv = 1.f / sum;
        #pragma unroll
        for (int k = 0; k < 12; k++) s_a2[k] = s2[k] * inv;
    }
    __syncthreads();

    const float bdr = s_bdr;
    float4 uu = make_float4(0.f, 0.f, 0.f, 0.f);
    float4 rr = make_float4(bdr, bdr, bdr, bdr);
    #pragma unroll
    for (int k = 0; k < 12; k++) {
        const float a = s_a2[k], w = s_wdr[k];
        uu.x = fmaf(a, lf[k].x, uu.x); uu.y = fmaf(a, lf[k].y, uu.y);
        uu.z = fmaf(a, lf[k].z, uu.z); uu.w = fmaf(a, lf[k].w, uu.w);
        rr.x = fmaf(w, lf[k].x, rr.x); rr.y = fmaf(w, lf[k].y, rr.y);
        rr.z = fmaf(w, lf[k].z, rr.z); rr.w = fmaf(w, lf[k].w, rr.w);
    }
    const float4 gg = gfeat[b * 128 + j];
    rr.x += gg.x; rr.y += gg.y; rr.z += gg.z; rr.w += gg.w;

    __half2 ha = __floats2half2_rn(uu.x, uu.y);
    __half2 hb = __floats2half2_rn(uu.z, uu.w);
    uint2 pk;
    pk.x = *(uint32_t*)&ha;
    pk.y = *(uint32_t*)&hb;
    u_h[b * 128 + j] = pk;
    res[b * 128 + j] = rr;
}

// ================= launch =================
extern "C" void kernel_launch(void* const* d_in, const int* in_sizes, int n_in,
                              void* d_out, int out_size) {
    const float* gf  = (const float*)d_in[0];   // [B, F]
    const float* lf  = (const float*)d_in[1];   // [B, 12, F]
    const float* Wq  = (const float*)d_in[2];   // [F, H]
    const float* bq  = (const float*)d_in[3];   // [H]
    const float* Wk  = (const float*)d_in[4];   // [F, H]  (bk softmax-invariant: dropped)
    const float* Wv  = (const float*)d_in[6];   // [F, H]
    const float* bv  = (const float*)d_in[7];   // [H]
    const float* wdr = (const float*)d_in[8];   // [12]
    const float* bdr = (const float*)d_in[9];   // scalar
    const float* Wf  = (const float*)d_in[10];  // [2H, F]
    const float* bfv = (const float*)d_in[11];  // [F]
    float* out = (float*)d_out;

    float *t, *res, *WfT, *c0, *c, *S;
    __half *gfh, *uh, *M0h, *MMh;
    cudaGetSymbolAddress((void**)&t,   g_t);
    cudaGetSymbolAddress((void**)&res, g_res);
    cudaGetSymbolAddress((void**)&gfh, g_gfh);
    cudaGetSymbolAddress((void**)&uh,  g_uh);
    cudaGetSymbolAddress((void**)&M0h, g_M0h);
    cudaGetSymbolAddress((void**)&MMh, g_MMh);
    cudaGetSymbolAddress((void**)&WfT, g_WfT);
    cudaGetSymbolAddress((void**)&c0,  g_c0);
    cudaGetSymbolAddress((void**)&c,   g_c);
    cudaGetSymbolAddress((void**)&S,   g_S);

    // 1) gf -> fp16 (independent; do it first to overlap latency in graph replay)
    cvt_f2h<<<(BATCH * FDIM / 4 + 255) / 256, 256>>>(
        (const float4*)gf, (uint2*)gfh, BATCH * FDIM / 4);
    // 2) WfT = Wf^T
    transpose512<<<dim3(16, 16), 256>>>(Wf, WfT);
    // 3) scalars + folded bias vectors (needs WfT)
    prep_vec<<<128, 128>>>(wdr, bdr, bq, Wk, bv, WfT, bfv, c0, c, S);
    // 4) all three weight products (needs S for z=2; prep_vec wrote it)
    prep_all<<<dim3(8, 8, 3), 128>>>(Wk, Wq, WfT, Wv, S, M0h, MMh);
    // 5) t = gf_h @ M0 + c0   [B,512], K=512  (fp16 tensor cores)
    hgemm<16, false, false><<<dim3(FDIM / 128, BATCH / 128), 256>>>(
        gfh, nullptr, M0h, FDIM, c0, nullptr, t);
    // 6) row kernel: softmax weights, u (fp16), res
    row_fused_kernel<<<BATCH, 128>>>(
        (const float4*)lf, (const float4*)t, (const float4*)gf,
        wdr, bdr, (uint2*)uh, (float4*)res);
    // 7) out = relu([u|gf] @ MM + c) + res   [B,512], K=1024  (fp16 tensor cores)
    hgemm<32, true, true><<<dim3(FDIM / 128, BATCH / 128), 256>>>(
        uh, gfh, MMh, 2 * FDIM, c, res, out);
}

// round 6
// speedup vs baseline: 1.5989x; 1.0326x over previous
#include <cuda_runtime.h>
#include <cuda_fp16.h>
#include <cstdint>

// Problem constants
#define BATCH 16384
#define NLOC  12
#define FDIM  512
#define HDIM  256

// ---------------- scratch (device globals; no runtime allocation) ----------------
__device__ __half g_th  [BATCH * FDIM];     // gf @ M0 + c0  (fp16)
__device__ float  g_res [BATCH * FDIM];     // lf_mean + b_dr + gf
__device__ __half g_gfh [BATCH * FDIM];     // gf as fp16
__device__ __half g_uh  [BATCH * FDIM];     // softmax-weighted local rows (fp16)
__device__ __half g_M0h [FDIM * FDIM];      // (Wq@Wk^T)^T  [N=512, K=512] fp16
__device__ __half g_MMh [FDIM * 2 * FDIM];  // [(Wv@WfTop)^T | S*(Wv@WfBot)^T] fp16
__device__ float  g_WfT [FDIM * FDIM];      // Wf^T
__device__ float  g_c0  [FDIM];
__device__ float  g_c   [FDIM];
__device__ float  g_S   [1];

// ---------------- PTX helpers ----------------
__device__ __forceinline__ void cp_async16(void* smem, const void* gmem) {
    unsigned s = (unsigned)__cvta_generic_to_shared(smem);
    asm volatile("cp.async.cg.shared.global [%0], [%1], 16;\n" :: "r"(s), "l"(gmem));
}
__device__ __forceinline__ void cp_commit() { asm volatile("cp.async.commit_group;\n"); }
__device__ __forceinline__ void cp_wait0() { asm volatile("cp.async.wait_group 0;\n"); }
__device__ __forceinline__ void cp_wait2() { asm volatile("cp.async.wait_group 2;\n"); }

__device__ __forceinline__ uint32_t f2tf32(float f) {
    uint32_t r;
    asm("cvt.rna.tf32.f32 %0, %1;" : "=r"(r) : "f"(f));
    return r;
}
__device__ __forceinline__ void mma_tf32(float c[4], const uint32_t a[4], const uint32_t b[2]) {
    asm volatile(
        "mma.sync.aligned.m16n8k8.row.col.f32.tf32.tf32.f32 "
        "{%0,%1,%2,%3}, {%4,%5,%6,%7}, {%8,%9}, {%0,%1,%2,%3};\n"
        : "+f"(c[0]), "+f"(c[1]), "+f"(c[2]), "+f"(c[3])
        : "r"(a[0]), "r"(a[1]), "r"(a[2]), "r"(a[3]), "r"(b[0]), "r"(b[1]));
}
__device__ __forceinline__ void mma_f16(float c[4], const uint32_t a[4], const uint32_t b[2]) {
    asm volatile(
        "mma.sync.aligned.m16n8k16.row.col.f32.f16.f16.f32 "
        "{%0,%1,%2,%3}, {%4,%5,%6,%7}, {%8,%9}, {%0,%1,%2,%3};\n"
        : "+f"(c[0]), "+f"(c[1]), "+f"(c[2]), "+f"(c[3])
        : "r"(a[0]), "r"(a[1]), "r"(a[2]), "r"(a[3]), "r"(b[0]), "r"(b[1]));
}
__device__ __forceinline__ void ldsm4(uint32_t& r0, uint32_t& r1, uint32_t& r2, uint32_t& r3,
                                      uint32_t addr) {
    asm volatile("ldmatrix.sync.aligned.m8n8.x4.shared.b16 {%0,%1,%2,%3}, [%4];"
                 : "=r"(r0), "=r"(r1), "=r"(r2), "=r"(r3) : "r"(addr));
}

// ================= fp16 tensor-core GEMM, 4-stage cp.async pipeline ============
// C[M,512] = A[M,K] @ Bt^T + cvec; block tile 128x128, BK=32, 256 thr (8 warps 32m x 64n).
// A half [*,512] row-major; SPLIT: kt >= KT/2 reads A1. Bt half [N,K] row-major.
// OUTH: C is half (no res). FINAL: C = relu(D + cvec) + res (fp32 out).
// Dynamic smem: 4 stages x (As 5120 + Bs 5120) halves = 81920 B.
#define HG_STAGE_H 10240          // halves per stage (A then B)
template<int KT, bool SPLIT, bool FINAL, bool OUTH>
__global__ void __launch_bounds__(256, 2) hgemm(
    const __half* __restrict__ A0, const __half* __restrict__ A1,
    const __half* __restrict__ Bt, int ldb,
    const float* __restrict__ cvec, const float* __restrict__ res,
    void* __restrict__ Cout)
{
    extern __shared__ __half sm[];

    const int tid = threadIdx.x;
    const int wid = tid >> 5, lane = tid & 31;
    const int bm = blockIdx.y * 128, bn = blockIdx.x * 128;
    const int wm = (wid & 3) * 32, wn = (wid >> 2) * 64;
    const int g = lane >> 2, tq = lane & 3;

    float acc[2][8][4];
    #pragma unroll
    for (int mi = 0; mi < 2; mi++)
        #pragma unroll
        for (int ni = 0; ni < 8; ni++)
            #pragma unroll
            for (int i = 0; i < 4; i++) acc[mi][ni][i] = 0.f;

    // ldmatrix per-lane address components
    const int q = lane >> 3, r8 = lane & 7;
    const int qRow = (q & 1) * 8 + r8;
    const int qCol = (q >> 1) * 8;
    const uint32_t smBase = (uint32_t)__cvta_generic_to_shared(&sm[0]);
    const uint32_t aLane = ((wm + qRow) * 40 + qCol) * 2;
    const uint32_t bLane = ((wn + qRow) * 40 + qCol) * 2 + 5120 * 2;

    const int row0 = tid >> 2, c16 = tid & 3;

    auto load_tile = [&](int kt, int st) {
        const __half* Ag = A0;
        int ktA = kt;
        if (SPLIT && kt >= KT / 2) { Ag = A1; ktA = kt - KT / 2; }
        __half* As = sm + st * HG_STAGE_H;
        __half* Bs = As + 5120;
        #pragma unroll
        for (int i = 0; i < 2; i++) {
            int row = row0 + i * 64;
            cp_async16(&As[row * 40 + c16 * 8],
                       Ag + (size_t)(bm + row) * 512 + ktA * 32 + c16 * 8);
            cp_async16(&Bs[row * 40 + c16 * 8],
                       Bt + (size_t)(bn + row) * ldb + kt * 32 + c16 * 8);
        }
    };

    load_tile(0, 0); cp_commit();
    load_tile(1, 1); cp_commit();
    load_tile(2, 2); cp_commit();

    for (int kt = 0; kt < KT; ++kt) {
        const int st = kt & 3;
        cp_wait2();
        __syncthreads();
        // prefetch kt+3 (into the buffer consumed at iteration kt-1)
        if (kt + 3 < KT) load_tile(kt + 3, (kt + 3) & 3);
        cp_commit();   // unconditional: keeps group-count arithmetic valid in tail

        const uint32_t aB = smBase + st * (HG_STAGE_H * 2) + aLane;
        const uint32_t bB = smBase + st * (HG_STAGE_H * 2) + bLane;
        #pragma unroll
        for (int ks = 0; ks < 32; ks += 16) {
            uint32_t aF[2][4], bF[8][2];
            #pragma unroll
            for (int mi = 0; mi < 2; mi++)
                ldsm4(aF[mi][0], aF[mi][1], aF[mi][2], aF[mi][3],
                      aB + (mi * 16 * 40 + ks) * 2);
            #pragma unroll
            for (int nb = 0; nb < 4; nb++) {
                uint32_t t0, t1, t2, t3;
                ldsm4(t0, t1, t2, t3, bB + (nb * 16 * 40 + ks) * 2);
                bF[2 * nb][0] = t0; bF[2 * nb + 1][0] = t1;
                bF[2 * nb][1] = t2; bF[2 * nb + 1][1] = t3;
            }
            #pragma unroll
            for (int mi = 0; mi < 2; mi++)
                #pragma unroll
                for (int ni = 0; ni < 8; ni++)
                    mma_f16(acc[mi][ni], aF[mi], bF[ni]);
        }
        __syncthreads();
    }

    // epilogue
    #pragma unroll
    for (int mi = 0; mi < 2; mi++)
        #pragma unroll
        for (int ni = 0; ni < 8; ni++) {
            int row = bm + wm + mi * 16 + g;
            int col = bn + wn + ni * 8 + 2 * tq;
            float b0 = cvec[col], b1 = cvec[col + 1];
            float v0 = acc[mi][ni][0] + b0, v1 = acc[mi][ni][1] + b1;
            float v2 = acc[mi][ni][2] + b0, v3 = acc[mi][ni][3] + b1;
            size_t o0 = (size_t)row * 512 + col;
            size_t o1 = (size_t)(row + 8) * 512 + col;
            if (OUTH) {
                __half* Ch = (__half*)Cout;
                __half2 h0 = __floats2half2_rn(v0, v1);
                __half2 h1 = __floats2half2_rn(v2, v3);
                *(__half2*)(Ch + o0) = h0;
                *(__half2*)(Ch + o1) = h1;
            } else {
                float* Cf = (float*)Cout;
                if (FINAL) {
                    const float2 r0 = *(const float2*)(res + o0);
                    const float2 r1 = *(const float2*)(res + o1);
                    v0 = fmaxf(v0, 0.f) + r0.x;
                    v1 = fmaxf(v1, 0.f) + r0.y;
                    v2 = fmaxf(v2, 0.f) + r1.x;
                    v3 = fmaxf(v3, 0.f) + r1.y;
                }
                *(float2*)(Cf + o0) = make_float2(v0, v1);
                *(float2*)(Cf + o1) = make_float2(v2, v3);
            }
        }
}

// ================= combined prep GEMMs — single-shot K=256 load ================
// 64x64 tiles, 128 threads, tf32 mma, fp16 out. Whole K strip loaded with ONE
// commit/wait (one DRAM round trip), then 32 mma-steps with no inner barriers.
// smem: 2 ops x 16 kt x 64 rows x 20 floats = 163840 B (dynamic).
// z=0: M0h = Wk·Wq^T ; z=1: MMh[:, :512] = WfT_top·Wv^T ; z=2: MMh[:, 512:] = S*WfT_bot·Wv^T
#define PREP_OP_F 20480   // floats per operand block
__global__ void __launch_bounds__(128) prep_all(
    const float* __restrict__ Wk, const float* __restrict__ Wq,
    const float* __restrict__ WfT, const float* __restrict__ Wv,
    const float* __restrict__ Sptr,
    __half* __restrict__ M0h, __half* __restrict__ MMh)
{
    extern __shared__ float smf[];
    float* As = smf;               // [kt][row][20]
    float* Bs = smf + PREP_OP_F;

    const int z = blockIdx.z;
    const float *A, *Bm;
    __half* C;
    int lda, ldc;
    float alpha = 1.f;
    if (z == 0)      { A = Wk;        lda = 256; Bm = Wq; C = M0h;       ldc = 512;  }
    else if (z == 1) { A = WfT;       lda = 512; Bm = Wv; C = MMh;       ldc = 1024; }
    else             { A = WfT + 256; lda = 512; Bm = Wv; C = MMh + 512; ldc = 1024;
                       alpha = Sptr[0]; }

    const int tid = threadIdx.x;
    const int bm = blockIdx.y * 64, bn = blockIdx.x * 64;
    const int lane = tid & 31, wid = tid >> 5;
    const int wm = (wid & 1) * 32, wn = (wid >> 1) * 32;
    const int g = lane >> 2, tq = lane & 3;

    // load entire 64x256 strips (4096 float4 chunks per operand, 32/thread)
    #pragma unroll
    for (int i = 0; i < 32; i++) {
        int ch = i * 128 + tid;
        int kt = ch >> 8, rem = ch & 255;
        int row = rem >> 2, c4 = (rem & 3) << 2;
        cp_async16(&As[kt * 1280 + row * 20 + c4], A + (size_t)(bm + row) * lda + kt * 16 + c4);
        cp_async16(&Bs[kt * 1280 + row * 20 + c4], Bm + (size_t)(bn + row) * 256 + kt * 16 + c4);
    }
    cp_commit();

    float acc[2][4][4];
    #pragma unroll
    for (int mi = 0; mi < 2; mi++)
        #pragma unroll
        for (int ni = 0; ni < 4; ni++)
            #pragma unroll
            for (int i = 0; i < 4; i++) acc[mi][ni][i] = 0.f;

    cp_wait0();
    __syncthreads();

    for (int kt = 0; kt < 16; ++kt) {
        const float* Ak = As + kt * 1280;
        const float* Bk = Bs + kt * 1280;
        #pragma unroll
        for (int ks = 0; ks < 16; ks += 8) {
            uint32_t aF[2][4], bF[4][2];
            #pragma unroll
            for (int mi = 0; mi < 2; mi++) {
                const float* ap = &Ak[(wm + mi * 16 + g) * 20 + ks + tq];
                aF[mi][0] = f2tf32(ap[0]);
                aF[mi][1] = f2tf32(ap[160]);
                aF[mi][2] = f2tf32(ap[4]);
                aF[mi][3] = f2tf32(ap[164]);
            }
            #pragma unroll
            for (int ni = 0; ni < 4; ni++) {
                const float* bp = &Bk[(wn + ni * 8 + g) * 20 + ks + tq];
                bF[ni][0] = f2tf32(bp[0]);
                bF[ni][1] = f2tf32(bp[4]);
            }
            #pragma unroll
            for (int mi = 0; mi < 2; mi++)
                #pragma unroll
                for (int ni = 0; ni < 4; ni++)
                    mma_tf32(acc[mi][ni], aF[mi], bF[ni]);
        }
    }

    #pragma unroll
    for (int mi = 0; mi < 2; mi++)
        #pragma unroll
        for (int ni = 0; ni < 4; ni++) {
            int r0 = bm + wm + mi * 16 + g;
            int cc = bn + wn + ni * 8 + 2 * tq;
            size_t o0 = (size_t)r0 * ldc + cc;
            size_t o1 = (size_t)(r0 + 8) * ldc + cc;
            C[o0]     = __float2half(acc[mi][ni][0] * alpha);
            C[o0 + 1] = __float2half(acc[mi][ni][1] * alpha);
            C[o1]     = __float2half(acc[mi][ni][2] * alpha);
            C[o1 + 1] = __float2half(acc[mi][ni][3] * alpha);
        }
}

// ================= prep: S, c0, c  (warp-per-f, coalesced via WfT) =============
__global__ void __launch_bounds__(128) prep_vec(
    const float* __restrict__ wdr, const float* __restrict__ bdrp,
    const float* __restrict__ bq, const float* __restrict__ Wk,
    const float* __restrict__ bv, const float* __restrict__ WfT,
    const float* __restrict__ bfv,
    float* __restrict__ c0, float* __restrict__ c, float* __restrict__ Sout)
{
    const int wid = threadIdx.x >> 5, lane = threadIdx.x & 31;
    const int f = blockIdx.x * 4 + wid;
    float S = (lane < NLOC) ? wdr[lane] : 0.f;
    #pragma unroll
    for (int off = 16; off > 0; off >>= 1) S += __shfl_xor_sync(0xffffffffu, S, off);
    const float bd = bdrp[0];
    if (blockIdx.x == 0 && threadIdx.x == 0) Sout[0] = S;

    float a0 = 0.f, a1 = 0.f;
    for (int h = lane; h < HDIM; h += 32) {
        a0 = fmaf(bq[h], Wk[f * HDIM + h], a0);
        const float bvh = bv[h];
        a1 = fmaf(bvh, WfT[f * FDIM + h], a1);
        a1 = fmaf(fmaf(S, bvh, bd), WfT[f * FDIM + HDIM + h], a1);
    }
    #pragma unroll
    for (int off = 16; off > 0; off >>= 1) {
        a0 += __shfl_xor_sync(0xffffffffu, a0, off);
        a1 += __shfl_xor_sync(0xffffffffu, a1, off);
    }
    if (lane == 0) {
        c0[f] = a0;
        c[f]  = a1 + bfv[f];
    }
}

// ================= transpose Wf -> WfT =================
__global__ void __launch_bounds__(256) transpose512(const float* __restrict__ in,
                                                    float* __restrict__ out)
{
    __shared__ float tileS[32][33];
    const int bx = blockIdx.x * 32, by = blockIdx.y * 32;
    const int tx = threadIdx.x & 31, ty = threadIdx.x >> 5;
    #pragma unroll
    for (int i = 0; i < 32; i += 8)
        tileS[ty + i][tx] = in[(size_t)(by + ty + i) * FDIM + bx + tx];
    __syncthreads();
    #pragma unroll
    for (int i = 0; i < 32; i += 8)
        out[(size_t)(bx + ty + i) * FDIM + by + tx] = tileS[tx][ty + i];
}

// ================= fp32 -> fp16 bulk convert =================
__global__ void __launch_bounds__(256) cvt_f2h(const float4* __restrict__ in,
                                               uint2* __restrict__ out, int n4)
{
    int i = blockIdx.x * blockDim.x + threadIdx.x;
    if (i < n4) {
        float4 v = in[i];
        __half2 h0 = __floats2half2_rn(v.x, v.y);
        __half2 h1 = __floats2half2_rn(v.z, v.w);
        uint2 pk;
        pk.x = *(uint32_t*)&h0;
        pk.y = *(uint32_t*)&h1;
        out[i] = pk;
    }
}

// ================= fused per-row kernel (t in fp16) =================
__global__ void __launch_bounds__(128) row_fused_kernel(
    const float4* __restrict__ local, const uint2* __restrict__ t_h,
    const float4* __restrict__ gfeat,
    const float* __restrict__ wdr, const float* __restrict__ bdrp,
    uint2* __restrict__ u_h, float4* __restrict__ res)
{
    const int b = blockIdx.x, j = threadIdx.x;
    __shared__ float s_wdr[12], s_red[4][12], s_a2[12], s_bdr;
    if (j < 12) s_wdr[j] = wdr[j];
    if (j == 0) s_bdr = bdrp[0];

    const uint2 tp = t_h[b * 128 + j];
    const float2 t0 = __half22float2(*(const __half2*)&tp.x);
    const float2 t1 = __half22float2(*(const __half2*)&tp.y);
    const float4 tv = make_float4(t0.x, t0.y, t1.x, t1.y);

    float4 lf[12];
    float p[12];
    #pragma unroll
    for (int k = 0; k < 12; k++) {
        lf[k] = local[(size_t)(b * 12 + k) * 128 + j];
        p[k] = lf[k].x * tv.x + lf[k].y * tv.y + lf[k].z * tv.z + lf[k].w * tv.w;
    }
    #pragma unroll
    for (int off = 16; off > 0; off >>= 1)
        #pragma unroll
        for (int k = 0; k < 12; k++)
            p[k] += __shfl_xor_sync(0xffffffffu, p[k], off);
    if ((j & 31) == 0) {
        #pragma unroll
        for (int k = 0; k < 12; k++) s_red[j >> 5][k] = p[k];
    }
    __syncthreads();
    if (j == 0) {
        float s2[12], mx = -1e30f;
        #pragma unroll
        for (int k = 0; k < 12; k++) {
            s2[k] = (s_red[0][k] + s_red[1][k] + s_red[2][k] + s_red[3][k]) * 0.0625f;
            mx = fmaxf(mx, s2[k]);
        }
        float sum = 0.f;
        #pragma unroll
        for (int k = 0; k < 12; k++) { s2[k] = __expf(s2[k] - mx); sum += s2[k]; }
        const float inv = 1.f / sum;
        #pragma unroll
        for (int k = 0; k < 12; k++) s_a2[k] = s2[k] * inv;
    }
    __syncthreads();

    const float bdr = s_bdr;
    float4 uu = make_float4(0.f, 0.f, 0.f, 0.f);
    float4 rr = make_float4(bdr, bdr, bdr, bdr);
    #pragma unroll
    for (int k = 0; k < 12; k++) {
        const float a = s_a2[k], w = s_wdr[k];
        uu.x = fmaf(a, lf[k].x, uu.x); uu.y = fmaf(a, lf[k].y, uu.y);
        uu.z = fmaf(a, lf[k].z, uu.z); uu.w = fmaf(a, lf[k].w, uu.w);
        rr.x = fmaf(w, lf[k].x, rr.x); rr.y = fmaf(w, lf[k].y, rr.y);
        rr.z = fmaf(w, lf[k].z, rr.z); rr.w = fmaf(w, lf[k].w, rr.w);
    }
    const float4 gg = gfeat[b * 128 + j];
    rr.x += gg.x; rr.y += gg.y; rr.z += gg.z; rr.w += gg.w;

    __half2 ha = __floats2half2_rn(uu.x, uu.y);
    __half2 hb = __floats2half2_rn(uu.z, uu.w);
    uint2 pk;
    pk.x = *(uint32_t*)&ha;
    pk.y = *(uint32_t*)&hb;
    u_h[b * 128 + j] = pk;
    res[b * 128 + j] = rr;
}

// ================= launch =================
static constexpr int HG_SMEM = 4 * HG_STAGE_H * 2;        // 81920 B
static constexpr int PREP_SMEM = 2 * PREP_OP_F * 4;       // 163840 B

extern "C" void kernel_launch(void* const* d_in, const int* in_sizes, int n_in,
                              void* d_out, int out_size) {
    const float* gf  = (const float*)d_in[0];   // [B, F]
    const float* lf  = (const float*)d_in[1];   // [B, 12, F]
    const float* Wq  = (const float*)d_in[2];   // [F, H]
    const float* bq  = (const float*)d_in[3];   // [H]
    const float* Wk  = (const float*)d_in[4];   // [F, H]  (bk softmax-invariant: dropped)
    const float* Wv  = (const float*)d_in[6];   // [F, H]
    const float* bv  = (const float*)d_in[7];   // [H]
    const float* wdr = (const float*)d_in[8];   // [12]
    const float* bdr = (const float*)d_in[9];   // scalar
    const float* Wf  = (const float*)d_in[10];  // [2H, F]
    const float* bfv = (const float*)d_in[11];  // [F]
    float* out = (float*)d_out;

    float *res, *WfT, *c0, *c, *S;
    __half *th, *gfh, *uh, *M0h, *MMh;
    cudaGetSymbolAddress((void**)&th,  g_th);
    cudaGetSymbolAddress((void**)&res, g_res);
    cudaGetSymbolAddress((void**)&gfh, g_gfh);
    cudaGetSymbolAddress((void**)&uh,  g_uh);
    cudaGetSymbolAddress((void**)&M0h, g_M0h);
    cudaGetSymbolAddress((void**)&MMh, g_MMh);
    cudaGetSymbolAddress((void**)&WfT, g_WfT);
    cudaGetSymbolAddress((void**)&c0,  g_c0);
    cudaGetSymbolAddress((void**)&c,   g_c);
    cudaGetSymbolAddress((void**)&S,   g_S);

    cudaFuncSetAttribute(hgemm<16, false, false, true>,
                         cudaFuncAttributeMaxDynamicSharedMemorySize, HG_SMEM);
    cudaFuncSetAttribute(hgemm<32, true, true, false>,
                         cudaFuncAttributeMaxDynamicSharedMemorySize, HG_SMEM);
    cudaFuncSetAttribute(prep_all,
                         cudaFuncAttributeMaxDynamicSharedMemorySize, PREP_SMEM);

    // 1) gf -> fp16
    cvt_f2h<<<(BATCH * FDIM / 4 + 255) / 256, 256>>>(
        (const float4*)gf, (uint2*)gfh, BATCH * FDIM / 4);
    // 2) WfT = Wf^T
    transpose512<<<dim3(16, 16), 256>>>(Wf, WfT);
    // 3) scalars + folded bias vectors (needs WfT)
    prep_vec<<<128, 128>>>(wdr, bdr, bq, Wk, bv, WfT, bfv, c0, c, S);
    // 4) all three weight products (single-shot K loads)
    prep_all<<<dim3(8, 8, 3), 128, PREP_SMEM>>>(Wk, Wq, WfT, Wv, S, M0h, MMh);
    // 5) t = gf_h @ M0 + c0 -> fp16   [B,512], K=512
    hgemm<16, false, false, true><<<dim3(FDIM / 128, BATCH / 128), 256, HG_SMEM>>>(
        gfh, nullptr, M0h, FDIM, c0, nullptr, th);
    // 6) row kernel: softmax weights, u (fp16), res
    row_fused_kernel<<<BATCH, 128>>>(
        (const float4*)lf, (const uint2*)th, (const float4*)gf,
        wdr, bdr, (uint2*)uh, (float4*)res);
    // 7) out = relu([u|gf] @ MM + c) + res   [B,512], K=1024
    hgemm<32, true, true, false><<<dim3(FDIM / 128, BATCH / 128), 256, HG_SMEM>>>(
        uh, gfh, MMh, 2 * FDIM, c, res, out);
}

// round 8
// speedup vs baseline: 1.6554x; 1.0353x over previous
#include <cuda_runtime.h>
#include <cuda_fp16.h>
#include <cstdint>

// Problem constants
#define BATCH 16384
#define NLOC  12
#define FDIM  512
#define HDIM  256

// ---------------- scratch (device globals; no runtime allocation) ----------------
__device__ __half g_th  [BATCH * FDIM];     // gf @ M0 + c0  (fp16)
__device__ float  g_res [BATCH * FDIM];     // lf_mean + b_dr
__device__ __half g_gfh [BATCH * FDIM];     // gf as fp16
__device__ __half g_uh  [BATCH * FDIM];     // softmax-weighted local rows (fp16)
__device__ __half g_M0h [FDIM * FDIM];      // (Wq@Wk^T)^T  [N=512, K=512] fp16
__device__ __half g_MMh [FDIM * 2 * FDIM];  // [(Wv@WfTop)^T | S*(Wv@WfBot)^T] fp16
__device__ float  g_WfT [FDIM * FDIM];      // Wf^T (fp32, for prep_vec)
__device__ __half g_WfTh[FDIM * FDIM];      // Wf^T (fp16, for prep GEMMs)
__device__ __half g_Wqh [FDIM * HDIM];
__device__ __half g_Wkh [FDIM * HDIM];
__device__ __half g_Wvh [FDIM * HDIM];
__device__ float  g_c0  [FDIM];
__device__ float  g_c   [FDIM];
__device__ float  g_S   [1];

// ---------------- PTX helpers ----------------
__device__ __forceinline__ void cp_async16(void* smem, const void* gmem) {
    unsigned s = (unsigned)__cvta_generic_to_shared(smem);
    asm volatile("cp.async.cg.shared.global [%0], [%1], 16;\n" :: "r"(s), "l"(gmem));
}
__device__ __forceinline__ void cp_commit() { asm volatile("cp.async.commit_group;\n"); }
__device__ __forceinline__ void cp_wait2() { asm volatile("cp.async.wait_group 2;\n"); }

__device__ __forceinline__ void mma_f16(float c[4], const uint32_t a[4], const uint32_t b[2]) {
    asm volatile(
        "mma.sync.aligned.m16n8k16.row.col.f32.f16.f16.f32 "
        "{%0,%1,%2,%3}, {%4,%5,%6,%7}, {%8,%9}, {%0,%1,%2,%3};\n"
        : "+f"(c[0]), "+f"(c[1]), "+f"(c[2]), "+f"(c[3])
        : "r"(a[0]), "r"(a[1]), "r"(a[2]), "r"(a[3]), "r"(b[0]), "r"(b[1]));
}
__device__ __forceinline__ void ldsm4(uint32_t& r0, uint32_t& r1, uint32_t& r2, uint32_t& r3,
                                      uint32_t addr) {
    asm volatile("ldmatrix.sync.aligned.m8n8.x4.shared.b16 {%0,%1,%2,%3}, [%4];"
                 : "=r"(r0), "=r"(r1), "=r"(r2), "=r"(r3) : "r"(addr));
}

#define HG_STAGE_H 10240          // halves per stage (A 5120 then B 5120)

// ================= fp16 tensor-core GEMM, 4-stage cp.async pipeline ============
// C[M,512] = A[M,K] @ Bt^T + cvec; block tile 128x128, BK=32, 256 thr (8 warps 32m x 64n).
// A half [*,512] row-major; SPLIT: kt >= KT/2 reads A1. Bt half [N,K] row-major.
// OUTH: C half, no res. FINAL: C = relu(D + cvec) + res + add2 (fp32 out).
template<int KT, bool SPLIT, bool FINAL, bool OUTH>
__global__ void __launch_bounds__(256, 2) hgemm(
    const __half* __restrict__ A0, const __half* __restrict__ A1,
    const __half* __restrict__ Bt, int ldb,
    const float* __restrict__ cvec, const float* __restrict__ res,
    const float* __restrict__ add2,
    void* __restrict__ Cout)
{
    extern __shared__ __half sm[];

    const int tid = threadIdx.x;
    const int wid = tid >> 5, lane = tid & 31;
    const int bm = blockIdx.y * 128, bn = blockIdx.x * 128;
    const int wm = (wid & 3) * 32, wn = (wid >> 2) * 64;
    const int g = lane >> 2, tq = lane & 3;

    float acc[2][8][4];
    #pragma unroll
    for (int mi = 0; mi < 2; mi++)
        #pragma unroll
        for (int ni = 0; ni < 8; ni++)
            #pragma unroll
            for (int i = 0; i < 4; i++) acc[mi][ni][i] = 0.f;

    const int q = lane >> 3, r8 = lane & 7;
    const int qRow = (q & 1) * 8 + r8;
    const int qCol = (q >> 1) * 8;
    const uint32_t smBase = (uint32_t)__cvta_generic_to_shared(&sm[0]);
    const uint32_t aLane = ((wm + qRow) * 40 + qCol) * 2;
    const uint32_t bLane = ((wn + qRow) * 40 + qCol) * 2 + 5120 * 2;

    const int row0 = tid >> 2, c16 = tid & 3;

    auto load_tile = [&](int kt, int st) {
        const __half* Ag = A0;
        int ktA = kt;
        if (SPLIT && kt >= KT / 2) { Ag = A1; ktA = kt - KT / 2; }
        __half* As = sm + st * HG_STAGE_H;
        __half* Bs = As + 5120;
        #pragma unroll
        for (int i = 0; i < 2; i++) {
            int row = row0 + i * 64;
            cp_async16(&As[row * 40 + c16 * 8],
                       Ag + (size_t)(bm + row) * 512 + ktA * 32 + c16 * 8);
            cp_async16(&Bs[row * 40 + c16 * 8],
                       Bt + (size_t)(bn + row) * ldb + kt * 32 + c16 * 8);
        }
    };

    load_tile(0, 0); cp_commit();
    load_tile(1, 1); cp_commit();
    load_tile(2, 2); cp_commit();

    for (int kt = 0; kt < KT; ++kt) {
        const int st = kt & 3;
        cp_wait2();
        __syncthreads();
        if (kt + 3 < KT) load_tile(kt + 3, (kt + 3) & 3);
        cp_commit();

        const uint32_t aB = smBase + st * (HG_STAGE_H * 2) + aLane;
        const uint32_t bB = smBase + st * (HG_STAGE_H * 2) + bLane;
        #pragma unroll
        for (int ks = 0; ks < 32; ks += 16) {
            uint32_t aF[2][4], bF[8][2];
            #pragma unroll
            for (int mi = 0; mi < 2; mi++)
                ldsm4(aF[mi][0], aF[mi][1], aF[mi][2], aF[mi][3],
                      aB + (mi * 16 * 40 + ks) * 2);
            #pragma unroll
            for (int nb = 0; nb < 4; nb++) {
                uint32_t t0, t1, t2, t3;
                ldsm4(t0, t1, t2, t3, bB + (nb * 16 * 40 + ks) * 2);
                bF[2 * nb][0] = t0; bF[2 * nb + 1][0] = t1;
                bF[2 * nb][1] = t2; bF[2 * nb + 1][1] = t3;
            }
            #pragma unroll
            for (int mi = 0; mi < 2; mi++)
                #pragma unroll
                for (int ni = 0; ni < 8; ni++)
                    mma_f16(acc[mi][ni], aF[mi], bF[ni]);
        }
        __syncthreads();
    }

    #pragma unroll
    for (int mi = 0; mi < 2; mi++)
        #pragma unroll
        for (int ni = 0; ni < 8; ni++) {
            int row = bm + wm + mi * 16 + g;
            int col = bn + wn + ni * 8 + 2 * tq;
            float b0 = cvec[col], b1 = cvec[col + 1];
            float v0 = acc[mi][ni][0] + b0, v1 = acc[mi][ni][1] + b1;
            float v2 = acc[mi][ni][2] + b0, v3 = acc[mi][ni][3] + b1;
            size_t o0 = (size_t)row * 512 + col;
            size_t o1 = (size_t)(row + 8) * 512 + col;
            if (OUTH) {
                __half* Ch = (__half*)Cout;
                *(__half2*)(Ch + o0) = __floats2half2_rn(v0, v1);
                *(__half2*)(Ch + o1) = __floats2half2_rn(v2, v3);
            } else {
                float* Cf = (float*)Cout;
                if (FINAL) {
                    const float2 r0 = *(const float2*)(res + o0);
                    const float2 r1 = *(const float2*)(res + o1);
                    const float2 g0 = *(const float2*)(add2 + o0);
                    const float2 g1 = *(const float2*)(add2 + o1);
                    v0 = fmaxf(v0, 0.f) + r0.x + g0.x;
                    v1 = fmaxf(v1, 0.f) + r0.y + g0.y;
                    v2 = fmaxf(v2, 0.f) + r1.x + g1.x;
                    v3 = fmaxf(v3, 0.f) + r1.y + g1.y;
                }
                *(float2*)(Cf + o0) = make_float2(v0, v1);
                *(float2*)(Cf + o1) = make_float2(v2, v3);
            }
        }
}

// ================= prep GEMMs: fp16 pipelined, all three products in one launch
// grid (4, 4, 3), 128x128 tiles, K=256 (KT=8).
// z=0: M0h[m][n] = Wk[m]·Wq[n]                  (ldc=512)
// z=1: MMh[m][n]       = WfT[m, 0:256]·Wv[n]    (ldc=1024)
// z=2: MMh[m][512 + n] = S * WfT[m,256:512]·Wv[n]
__global__ void __launch_bounds__(256, 2) prep_hgemm(
    const __half* __restrict__ Wk_h, const __half* __restrict__ Wq_h,
    const __half* __restrict__ WfTh, const __half* __restrict__ Wv_h,
    const float* __restrict__ Sptr,
    __half* __restrict__ M0h, __half* __restrict__ MMh)
{
    extern __shared__ __half sm[];
    constexpr int KT = 8;

    const int z = blockIdx.z;
    const __half *A, *Bt;
    __half* C;
    int lda, ldc;
    float alpha = 1.f;
    if (z == 0)      { A = Wk_h;        lda = 256; Bt = Wq_h; C = M0h;       ldc = 512;  }
    else if (z == 1) { A = WfTh;        lda = 512; Bt = Wv_h; C = MMh;       ldc = 1024; }
    else             { A = WfTh + 256;  lda = 512; Bt = Wv_h; C = MMh + 512; ldc = 1024;
                       alpha = Sptr[0]; }

    const int tid = threadIdx.x;
    const int wid = tid >> 5, lane = tid & 31;
    const int bm = blockIdx.y * 128, bn = blockIdx.x * 128;
    const int wm = (wid & 3) * 32, wn = (wid >> 2) * 64;
    const int g = lane >> 2, tq = lane & 3;

    float acc[2][8][4];
    #pragma unroll
    for (int mi = 0; mi < 2; mi++)
        #pragma unroll
        for (int ni = 0; ni < 8; ni++)
            #pragma unroll
            for (int i = 0; i < 4; i++) acc[mi][ni][i] = 0.f;

    const int q = lane >> 3, r8 = lane & 7;
    const int qRow = (q & 1) * 8 + r8;
    const int qCol = (q >> 1) * 8;
    const uint32_t smBase = (uint32_t)__cvta_generic_to_shared(&sm[0]);
    const uint32_t aLane = ((wm + qRow) * 40 + qCol) * 2;
    const uint32_t bLane = ((wn + qRow) * 40 + qCol) * 2 + 5120 * 2;

    const int row0 = tid >> 2, c16 = tid & 3;

    auto load_tile = [&](int kt, int st) {
        __half* As = sm + st * HG_STAGE_H;
        __half* Bs = As + 5120;
        #pragma unroll
        for (int i = 0; i < 2; i++) {
            int row = row0 + i * 64;
            cp_async16(&As[row * 40 + c16 * 8],
                       A + (size_t)(bm + row) * lda + kt * 32 + c16 * 8);
            cp_async16(&Bs[row * 40 + c16 * 8],
                       Bt + (size_t)(bn + row) * 256 + kt * 32 + c16 * 8);
        }
    };

    load_tile(0, 0); cp_commit();
    load_tile(1, 1); cp_commit();
    load_tile(2, 2); cp_commit();

    for (int kt = 0; kt < KT; ++kt) {
        const int st = kt & 3;
        cp_wait2();
        __syncthreads();
        if (kt + 3 < KT) load_tile(kt + 3, (kt + 3) & 3);
        cp_commit();

        const uint32_t aB = smBase + st * (HG_STAGE_H * 2) + aLane;
        const uint32_t bB = smBase + st * (HG_STAGE_H * 2) + bLane;
        #pragma unroll
        for (int ks = 0; ks < 32; ks += 16) {
            uint32_t aF[2][4], bF[8][2];
            #pragma unroll
            for (int mi = 0; mi < 2; mi++)
                ldsm4(aF[mi][0], aF[mi][1], aF[mi][2], aF[mi][3],
                      aB + (mi * 16 * 40 + ks) * 2);
            #pragma unroll
            for (int nb = 0; nb < 4; nb++) {
                uint32_t t0, t1, t2, t3;
                ldsm4(t0, t1, t2, t3, bB + (nb * 16 * 40 + ks) * 2);
                bF[2 * nb][0] = t0; bF[2 * nb + 1][0] = t1;
                bF[2 * nb][1] = t2; bF[2 * nb + 1][1] = t3;
            }
            #pragma unroll
            for (int mi = 0; mi < 2; mi++)
                #pragma unroll
                for (int ni = 0; ni < 8; ni++)
                    mma_f16(acc[mi][ni], aF[mi], bF[ni]);
        }
        __syncthreads();
    }

    #pragma unroll
    for (int mi = 0; mi < 2; mi++)
        #pragma unroll
        for (int ni = 0; ni < 8; ni++) {
            int row = bm + wm + mi * 16 + g;
            int col = bn + wn + ni * 8 + 2 * tq;
            size_t o0 = (size_t)row * ldc + col;
            size_t o1 = (size_t)(row + 8) * ldc + col;
            *(__half2*)(C + o0) = __floats2half2_rn(acc[mi][ni][0] * alpha,
                                                    acc[mi][ni][1] * alpha);
            *(__half2*)(C + o1) = __floats2half2_rn(acc[mi][ni][2] * alpha,
                                                    acc[mi][ni][3] * alpha);
        }
}

// ================= prep: S, c0, c  (warp-per-f, coalesced via WfT) =============
__global__ void __launch_bounds__(128) prep_vec(
    const float* __restrict__ wdr, const float* __restrict__ bdrp,
    const float* __restrict__ bq, const float* __restrict__ Wk,
    const float* __restrict__ bv, const float* __restrict__ WfT,
    const float* __restrict__ bfv,
    float* __restrict__ c0, float* __restrict__ c, float* __restrict__ Sout)
{
    const int wid = threadIdx.x >> 5, lane = threadIdx.x & 31;
    const int f = blockIdx.x * 4 + wid;
    float S = (lane < NLOC) ? wdr[lane] : 0.f;
    #pragma unroll
    for (int off = 16; off > 0; off >>= 1) S += __shfl_xor_sync(0xffffffffu, S, off);
    const float bd = bdrp[0];
    if (blockIdx.x == 0 && threadIdx.x == 0) Sout[0] = S;

    float a0 = 0.f, a1 = 0.f;
    for (int h = lane; h < HDIM; h += 32) {
        a0 = fmaf(bq[h], Wk[f * HDIM + h], a0);
        const float bvh = bv[h];
        a1 = fmaf(bvh, WfT[f * FDIM + h], a1);
        a1 = fmaf(fmaf(S, bvh, bd), WfT[f * FDIM + HDIM + h], a1);
    }
    #pragma unroll
    for (int off = 16; off > 0; off >>= 1) {
        a0 += __shfl_xor_sync(0xffffffffu, a0, off);
        a1 += __shfl_xor_sync(0xffffffffu, a1, off);
    }
    if (lane == 0) {
        c0[f] = a0;
        c[f]  = a1 + bfv[f];
    }
}

// ================= transpose Wf -> WfT (fp32) + WfTh (fp16) =================
__global__ void __launch_bounds__(256) transpose512h(const float* __restrict__ in,
                                                     float* __restrict__ out,
                                                     __half* __restrict__ outh)
{
    __shared__ float tileS[32][33];
    const int bx = blockIdx.x * 32, by = blockIdx.y * 32;
    const int tx = threadIdx.x & 31, ty = threadIdx.x >> 5;
    #pragma unroll
    for (int i = 0; i < 32; i += 8)
        tileS[ty + i][tx] = in[(size_t)(by + ty + i) * FDIM + bx + tx];
    __syncthreads();
    #pragma unroll
    for (int i = 0; i < 32; i += 8) {
        float v = tileS[tx][ty + i];
        size_t o = (size_t)(bx + ty + i) * FDIM + by + tx;
        out[o]  = v;
        outh[o] = __float2half(v);
    }
}

// ================= fp32 -> fp16 bulk convert =================
__global__ void __launch_bounds__(256) cvt_f2h(const float4* __restrict__ in,
                                               uint2* __restrict__ out, int n4)
{
    int i = blockIdx.x * blockDim.x + threadIdx.x;
    if (i < n4) {
        float4 v = in[i];
        __half2 h0 = __floats2half2_rn(v.x, v.y);
        __half2 h1 = __floats2half2_rn(v.z, v.w);
        uint2 pk;
        pk.x = *(uint32_t*)&h0;
        pk.y = *(uint32_t*)&h1;
        out[i] = pk;
    }
}

// convert Wq, Wk, Wv (each 512*256 fp32) in one launch; blockIdx.y selects matrix
__global__ void __launch_bounds__(256) cvt_w3(
    const float4* __restrict__ a, const float4* __restrict__ b,
    const float4* __restrict__ c,
    uint2* __restrict__ ah, uint2* __restrict__ bh, uint2* __restrict__ ch)
{
    const float4* in;
    uint2* out;
    if (blockIdx.y == 0)      { in = a; out = ah; }
    else if (blockIdx.y == 1) { in = b; out = bh; }
    else                      { in = c; out = ch; }
    int i = blockIdx.x * 256 + threadIdx.x;   // 128 blocks x 256 = 32768 = 512*256/4
    float4 v = in[i];
    __half2 h0 = __floats2half2_rn(v.x, v.y);
    __half2 h1 = __floats2half2_rn(v.z, v.w);
    uint2 pk;
    pk.x = *(uint32_t*)&h0;
    pk.y = *(uint32_t*)&h1;
    out[i] = pk;
}

// ================= fused per-row kernel (t fp16; no gf here anymore) ===========
__global__ void __launch_bounds__(128) row_fused_kernel(
    const float4* __restrict__ local, const uint2* __restrict__ t_h,
    const float* __restrict__ wdr, const float* __restrict__ bdrp,
    uint2* __restrict__ u_h, float4* __restrict__ res)
{
    const int b = blockIdx.x, j = threadIdx.x;
    __shared__ float s_wdr[12], s_red[4][12], s_a2[12], s_bdr;
    if (j < 12) s_wdr[j] = wdr[j];
    if (j == 0) s_bdr = bdrp[0];

    const uint2 tp = t_h[b * 128 + j];
    const float2 t0 = __half22float2(*(const __half2*)&tp.x);
    const float2 t1 = __half22float2(*(const __half2*)&tp.y);
    const float4 tv = make_float4(t0.x, t0.y, t1.x, t1.y);

    float4 lf[12];
    float p[12];
    #pragma unroll
    for (int k = 0; k < 12; k++) {
        lf[k] = local[(size_t)(b * 12 + k) * 128 + j];
        p[k] = lf[k].x * tv.x + lf[k].y * tv.y + lf[k].z * tv.z + lf[k].w * tv.w;
    }
    #pragma unroll
    for (int off = 16; off > 0; off >>= 1)
        #pragma unroll
        for (int k = 0; k < 12; k++)
            p[k] += __shfl_xor_sync(0xffffffffu, p[k], off);
    if ((j & 31) == 0) {
        #pragma unroll
        for (int k = 0; k < 12; k++) s_red[j >> 5][k] = p[k];
    }
    __syncthreads();
    if (j == 0) {
        float s2[12], mx = -1e30f;
        #pragma unroll
        for (int k = 0; k < 12; k++) {
            s2[k] = (s_red[0][k] + s_red[1][k] + s_red[2][k] + s_red[3][k]) * 0.0625f;
            mx = fmaxf(mx, s2[k]);
        }
        float sum = 0.f;
        #pragma unroll
        for (int k = 0; k < 12; k++) { s2[k] = __expf(s2[k] - mx); sum += s2[k]; }
        const float inv = 1.f / sum;
        #pragma unroll
        for (int k = 0; k < 12; k++) s_a2[k] = s2[k] * inv;
    }
    __syncthreads();

    const float bdr = s_bdr;
    float4 uu = make_float4(0.f, 0.f, 0.f, 0.f);
    float4 rr = make_float4(bdr, bdr, bdr, bdr);
    #pragma unroll
    for (int k = 0; k < 12; k++) {
        const float a = s_a2[k], w = s_wdr[k];
        uu.x = fmaf(a, lf[k].x, uu.x); uu.y = fmaf(a, lf[k].y, uu.y);
        uu.z = fmaf(a, lf[k].z, uu.z); uu.w = fmaf(a, lf[k].w, uu.w);
        rr.x = fmaf(w, lf[k].x, rr.x); rr.y = fmaf(w, lf[k].y, rr.y);
        rr.z = fmaf(w, lf[k].z, rr.z); rr.w = fmaf(w, lf[k].w, rr.w);
    }

    __half2 ha = __floats2half2_rn(uu.x, uu.y);
    __half2 hb = __floats2half2_rn(uu.z, uu.w);
    uint2 pk;
    pk.x = *(uint32_t*)&ha;
    pk.y = *(uint32_t*)&hb;
    u_h[b * 128 + j] = pk;
    res[b * 128 + j] = rr;
}

// ================= launch =================
static constexpr int HG_SMEM = 4 * HG_STAGE_H * 2;        // 81920 B

extern "C" void kernel_launch(void* const* d_in, const int* in_sizes, int n_in,
                              void* d_out, int out_size) {
    const float* gf  = (const float*)d_in[0];   // [B, F]
    const float* lf  = (const float*)d_in[1];   // [B, 12, F]
    const float* Wq  = (const float*)d_in[2];   // [F, H]
    const float* bq  = (const float*)d_in[3];   // [H]
    const float* Wk  = (const float*)d_in[4];   // [F, H]  (bk softmax-invariant: dropped)
    const float* Wv  = (const float*)d_in[6];   // [F, H]
    const float* bv  = (const float*)d_in[7];   // [H]
    const float* wdr = (const float*)d_in[8];   // [12]
    const float* bdr = (const float*)d_in[9];   // scalar
    const float* Wf  = (const float*)d_in[10];  // [2H, F]
    const float* bfv = (const float*)d_in[11];  // [F]
    float* out = (float*)d_out;

    float *res, *WfT, *c0, *c, *S;
    __half *th, *gfh, *uh, *M0h, *MMh, *WfTh, *Wqh, *Wkh, *Wvh;
    cudaGetSymbolAddress((void**)&th,   g_th);
    cudaGetSymbolAddress((void**)&res,  g_res);
    cudaGetSymbolAddress((void**)&gfh,  g_gfh);
    cudaGetSymbolAddress((void**)&uh,   g_uh);
    cudaGetSymbolAddress((void**)&M0h,  g_M0h);
    cudaGetSymbolAddress((void**)&MMh,  g_MMh);
    cudaGetSymbolAddress((void**)&WfT,  g_WfT);
    cudaGetSymbolAddress((void**)&WfTh, g_WfTh);
    cudaGetSymbolAddress((void**)&Wqh,  g_Wqh);
    cudaGetSymbolAddress((void**)&Wkh,  g_Wkh);
    cudaGetSymbolAddress((void**)&Wvh,  g_Wvh);
    cudaGetSymbolAddress((void**)&c0,   g_c0);
    cudaGetSymbolAddress((void**)&c,    g_c);
    cudaGetSymbolAddress((void**)&S,    g_S);

    cudaFuncSetAttribute(hgemm<16, false, false, true>,
                         cudaFuncAttributeMaxDynamicSharedMemorySize, HG_SMEM);
    cudaFuncSetAttribute(hgemm<32, true, true, false>,
                         cudaFuncAttributeMaxDynamicSharedMemorySize, HG_SMEM);
    cudaFuncSetAttribute(prep_hgemm,
                         cudaFuncAttributeMaxDynamicSharedMemorySize, HG_SMEM);

    // 1) gf -> fp16
    cvt_f2h<<<(BATCH * FDIM / 4 + 255) / 256, 256>>>(
        (const float4*)gf, (uint2*)gfh, BATCH * FDIM / 4);
    // 2) Wq, Wk, Wv -> fp16 (one launch)
    cvt_w3<<<dim3(128, 3), 256>>>(
        (const float4*)Wq, (const float4*)Wk, (const float4*)Wv,
        (uint2*)Wqh, (uint2*)Wkh, (uint2*)Wvh);
    // 3) WfT = Wf^T (fp32 + fp16)
    transpose512h<<<dim3(16, 16), 256>>>(Wf, WfT, WfTh);
    // 4) scalars + folded bias vectors (needs WfT)
    prep_vec<<<128, 128>>>(wdr, bdr, bq, Wk, bv, WfT, bfv, c0, c, S);
    // 5) all three weight products (fp16 HMMA pipeline, one wave)
    prep_hgemm<<<dim3(4, 4, 3), 256, HG_SMEM>>>(Wkh, Wqh, WfTh, Wvh, S, M0h, MMh);
    // 6) t = gf_h @ M0 + c0 -> fp16   [B,512], K=512
    hgemm<16, false, false, true><<<dim3(FDIM / 128, BATCH / 128), 256, HG_SMEM>>>(
        gfh, nullptr, M0h, FDIM, c0, nullptr, nullptr, th);
    // 7) row kernel: softmax weights, u (fp16), res = lf_mean + b_dr
    row_fused_kernel<<<BATCH, 128>>>(
        (const float4*)lf, (const uint2*)th, wdr, bdr, (uint2*)uh, (float4*)res);
    // 8) out = relu([u|gf] @ MM + c) + res + gf   [B,512], K=1024
    hgemm<32, true, true, false><<<dim3(FDIM / 128, BATCH / 128), 256, HG_SMEM>>>(
        uh, gfh, MMh, 2 * FDIM, c, res, gf, out);
}